// round 4
// baseline (speedup 1.0000x reference)
#include <cuda_runtime.h>
#include <math.h>

#define Bn 1024
#define Dn 512
#define Vn 128
#define Tn 201

// ---------------- device scratch ----------------
__device__ float g_h[Bn * Dn];          // h_t (read by logits)
__device__ float g_hxbuf[2][Bn * Dn];   // ping-pong: h_t + ctx (gates GEMM input)
__device__ float g_c[Bn * Dn];
__device__ float g_ctx[Bn * Dn];
__device__ float g_E2[Vn * 4 * Dn];     // embed @ W_ih^T + b_ih + b_hh
__device__ float g_pwT[Dn * Vn];        // proj_w transposed [K][V]
__device__ int   g_token[Bn];

// ---------------- packed fp32x2 helpers (Blackwell) ----------------
__device__ __forceinline__ unsigned long long pack2(float a) {
    unsigned long long r;
    asm("mov.b64 %0, {%1, %1};" : "=l"(r) : "f"(a));
    return r;
}
__device__ __forceinline__ void ffma2(unsigned long long& c, unsigned long long a, unsigned long long b) {
    asm("fma.rn.f32x2 %0, %1, %2, %0;" : "+l"(c) : "l"(a), "l"(b));
}
__device__ __forceinline__ float2 unpack2(unsigned long long v) {
    float2 f;
    asm("mov.b64 {%0, %1}, %2;" : "=f"(f.x), "=f"(f.y) : "l"(v));
    return f;
}
// exact activations (argmax feedback over 201 steps amplifies ulp noise; keep precise)
__device__ __forceinline__ float sigexact(float x) {
    return 1.f / (1.f + expf(-x));
}

// ---------------- P1: layernorm(h0) + attention context + init ----------------
__global__ void k_init(const float* __restrict__ fm, const float* __restrict__ pooled,
                       const float* __restrict__ gamma, const float* __restrict__ beta,
                       const float* __restrict__ attnw, const int* __restrict__ sos) {
    extern __shared__ float dyn[];
    float* sfm = dyn;            // 25088 floats
    float* swf = dyn + 25088;    // 512 floats
    __shared__ float red[256];
    __shared__ float saw[64];
    __shared__ float sstat[2];
    __shared__ float sh0[512];

    int b = blockIdx.x;
    int tid = threadIdx.x;

    const float4* fmb = (const float4*)(fm + (size_t)b * 25088);
    for (int i = tid; i < 6272; i += 256) ((float4*)sfm)[i] = fmb[i];
    for (int i = tid; i < 512; i += 256) swf[i] = attnw[i];

    // ---- layernorm of pooled[b] -> h0 (kept in smem)
    float x0 = pooled[b * Dn + tid];
    float x1 = pooled[b * Dn + 256 + tid];
    red[tid] = x0 + x1;
    __syncthreads();
    for (int s = 128; s > 0; s >>= 1) {
        if (tid < s) red[tid] += red[tid + s];
        __syncthreads();
    }
    if (tid == 0) sstat[0] = red[0] * (1.0f / Dn);
    __syncthreads();
    float mu = sstat[0];
    float d0 = x0 - mu, d1 = x1 - mu;
    red[tid] = d0 * d0 + d1 * d1;
    __syncthreads();
    for (int s = 128; s > 0; s >>= 1) {
        if (tid < s) red[tid] += red[tid + s];
        __syncthreads();
    }
    if (tid == 0) sstat[1] = rsqrtf(red[0] * (1.0f / Dn) + 1e-5f);
    __syncthreads();
    float rs = sstat[1];
    sh0[tid]       = d0 * rs * gamma[tid]       + beta[tid];
    sh0[256 + tid] = d1 * rs * gamma[256 + tid] + beta[256 + tid];

    // ---- scores[p] = sum_d FM[b][d][p] * wf[d]  (h-term cancels in softmax)
    if (tid < 49) {
        float sc = 0.f;
        #pragma unroll 8
        for (int d = 0; d < 512; d++) sc += sfm[d * 49 + tid] * swf[d];
        saw[tid] = sc;
    }
    __syncthreads();
    if (tid == 0) {
        float mx = -1e30f;
        for (int p = 0; p < 49; p++) mx = fmaxf(mx, saw[p]);
        float sm = 0.f;
        for (int p = 0; p < 49; p++) { float e = expf(saw[p] - mx); saw[p] = e; sm += e; }
        sstat[0] = 1.0f / sm;
    }
    __syncthreads();
    float inv = sstat[0];

    // ---- context[d]; hx0 = h0 + ctx; c = 0
    for (int d = tid; d < 512; d += 256) {
        float acc = 0.f;
        #pragma unroll
        for (int p = 0; p < 49; p++) acc += saw[p] * sfm[d * 49 + p];
        float ctx = acc * inv;
        g_ctx[b * Dn + d] = ctx;
        g_hxbuf[0][b * Dn + d] = ctx + sh0[d];
        g_c[b * Dn + d] = 0.f;
    }
    if (tid == 0) g_token[b] = *sos;
}

// ---------------- E2 = embed @ W_ih^T + b_ih + b_hh (one-time) ----------------
__global__ __launch_bounds__(256) void k_e2(const float* __restrict__ emb,
                                            const float* __restrict__ Wih,
                                            const float* __restrict__ bih,
                                            const float* __restrict__ bhh) {
    __shared__ __align__(16) float sA[16 * 68];
    __shared__ __align__(16) float sB[16 * 68];
    int m0 = blockIdx.y * 64;
    int n0 = blockIdx.x * 64;
    int tid = threadIdx.x;
    int tx = tid & 15, ty = tid >> 4;
    int lm = tid >> 2;
    int lk = (tid & 3) * 4;
    const float* Ap = emb + (size_t)(m0 + lm) * Dn + lk;
    const float* Bp = Wih + (size_t)(n0 + lm) * Dn + lk;
    float acc[4][4] = {};
    for (int kt = 0; kt < 512; kt += 16) {
        float4 a = *(const float4*)(Ap + kt);
        float4 bb = *(const float4*)(Bp + kt);
        sA[(lk + 0) * 68 + lm] = a.x;  sA[(lk + 1) * 68 + lm] = a.y;
        sA[(lk + 2) * 68 + lm] = a.z;  sA[(lk + 3) * 68 + lm] = a.w;
        sB[(lk + 0) * 68 + lm] = bb.x; sB[(lk + 1) * 68 + lm] = bb.y;
        sB[(lk + 2) * 68 + lm] = bb.z; sB[(lk + 3) * 68 + lm] = bb.w;
        __syncthreads();
        #pragma unroll
        for (int k = 0; k < 16; k++) {
            float4 av = *(const float4*)&sA[k * 68 + ty * 4];
            float4 bv = *(const float4*)&sB[k * 68 + tx * 4];
            float ar[4] = {av.x, av.y, av.z, av.w};
            float br[4] = {bv.x, bv.y, bv.z, bv.w};
            #pragma unroll
            for (int i = 0; i < 4; i++)
                #pragma unroll
                for (int j = 0; j < 4; j++) acc[i][j] += ar[i] * br[j];
        }
        __syncthreads();
    }
    int gj0 = n0 + tx * 4;
    float4 b1 = *(const float4*)&bih[gj0];
    float4 b2 = *(const float4*)&bhh[gj0];
    #pragma unroll
    for (int i = 0; i < 4; i++) {
        int gv = m0 + ty * 4 + i;
        float4 o;
        o.x = acc[i][0] + b1.x + b2.x;
        o.y = acc[i][1] + b1.y + b2.y;
        o.z = acc[i][2] + b1.z + b2.z;
        o.w = acc[i][3] + b1.w + b2.w;
        *(float4*)&g_E2[(size_t)gv * 2048 + gj0] = o;
    }
}

// ---------------- proj_w transpose (one-time) ----------------
__global__ void k_tw(const float* __restrict__ projw) {
    int idx = blockIdx.x * 256 + threadIdx.x;   // 65536 total
    int vv = idx >> 9;
    int kk = idx & 511;
    g_pwT[kk * 128 + vv] = projw[idx];
}

// ---------------- per-step: gates GEMM (f32x2) + fused LSTM cell ----------------
// tile: 64 batch x 128 gate-cols (gate-grouped: block owns d in [bx*32, bx*32+32)
// for ALL 4 gates). Thread tile 4x8 via packed f32x2 FMA.
// hx ping-pong: read g_hxbuf[hp], write g_hxbuf[hp^1]  (race-free across blocks)
__global__ __launch_bounds__(256, 2) void k_gates(int hp, const float* __restrict__ Whh) {
    const float* hxin = g_hxbuf[hp];
    float* hxout = g_hxbuf[hp ^ 1];
    __shared__ __align__(16) float sA[16 * 68];
    __shared__ __align__(16) float sB[16 * 132];
    __shared__ __align__(16) float sG[64 * 128];

    int bm0 = blockIdx.y * 64;
    int d0 = blockIdx.x * 32;
    int tid = threadIdx.x;
    int tx = tid & 15, ty = tid >> 4;

    // A loader: lm = row 0..63, lk = k-chunk of 4
    int lm = tid & 63, lk = (tid >> 6) * 4;
    const float* Ap = hxin + (size_t)(bm0 + lm) * Dn + lk;
    // B loader: nl = local col 0..127, kb = k-chunk of 8
    int nl = tid & 127, kb = (tid >> 7) * 8;
    int grow = (nl >> 5) * 512 + d0 + (nl & 31);
    const float* Bp = Whh + (size_t)grow * Dn + kb;

    unsigned long long acc[4][4];
    #pragma unroll
    for (int i = 0; i < 4; i++)
        #pragma unroll
        for (int j = 0; j < 4; j++) acc[i][j] = 0ULL;

    for (int kt = 0; kt < 512; kt += 16) {
        float4 a = *(const float4*)(Ap + kt);
        float4 b0 = *(const float4*)(Bp + kt);
        float4 b1 = *(const float4*)(Bp + kt + 4);
        sA[(lk + 0) * 68 + lm] = a.x;  sA[(lk + 1) * 68 + lm] = a.y;
        sA[(lk + 2) * 68 + lm] = a.z;  sA[(lk + 3) * 68 + lm] = a.w;
        sB[(kb + 0) * 132 + nl] = b0.x; sB[(kb + 1) * 132 + nl] = b0.y;
        sB[(kb + 2) * 132 + nl] = b0.z; sB[(kb + 3) * 132 + nl] = b0.w;
        sB[(kb + 4) * 132 + nl] = b1.x; sB[(kb + 5) * 132 + nl] = b1.y;
        sB[(kb + 6) * 132 + nl] = b1.z; sB[(kb + 7) * 132 + nl] = b1.w;
        __syncthreads();
        #pragma unroll
        for (int k = 0; k < 16; k++) {
            float4 av = *(const float4*)&sA[k * 68 + ty * 4];
            ulonglong2 q0 = *(const ulonglong2*)&sB[k * 132 + tx * 8];
            ulonglong2 q1 = *(const ulonglong2*)&sB[k * 132 + tx * 8 + 4];
            unsigned long long pa;
            pa = pack2(av.x);
            ffma2(acc[0][0], pa, q0.x); ffma2(acc[0][1], pa, q0.y);
            ffma2(acc[0][2], pa, q1.x); ffma2(acc[0][3], pa, q1.y);
            pa = pack2(av.y);
            ffma2(acc[1][0], pa, q0.x); ffma2(acc[1][1], pa, q0.y);
            ffma2(acc[1][2], pa, q1.x); ffma2(acc[1][3], pa, q1.y);
            pa = pack2(av.z);
            ffma2(acc[2][0], pa, q0.x); ffma2(acc[2][1], pa, q0.y);
            ffma2(acc[2][2], pa, q1.x); ffma2(acc[2][3], pa, q1.y);
            pa = pack2(av.w);
            ffma2(acc[3][0], pa, q0.x); ffma2(acc[3][1], pa, q0.y);
            ffma2(acc[3][2], pa, q1.x); ffma2(acc[3][3], pa, q1.y);
        }
        __syncthreads();
    }

    // epilogue: add gathered E2 row, stash tile in smem for gate exchange
    int gate = (tx * 8) >> 5;
    int ddb = (tx * 8) & 31;
    #pragma unroll
    for (int i = 0; i < 4; i++) {
        int gb = bm0 + ty * 4 + i;
        int tok = g_token[gb];
        const float* E = g_E2 + (size_t)tok * 2048 + gate * 512 + d0 + ddb;
        float4 e0 = *(const float4*)E;
        float4 e1 = *(const float4*)(E + 4);
        float2 p;
        float4 o0, o1;
        p = unpack2(acc[i][0]); o0.x = p.x + e0.x; o0.y = p.y + e0.y;
        p = unpack2(acc[i][1]); o0.z = p.x + e0.z; o0.w = p.y + e0.w;
        p = unpack2(acc[i][2]); o1.x = p.x + e1.x; o1.y = p.y + e1.y;
        p = unpack2(acc[i][3]); o1.z = p.x + e1.z; o1.w = p.y + e1.w;
        *(float4*)&sG[(ty * 4 + i) * 128 + tx * 8]     = o0;
        *(float4*)&sG[(ty * 4 + i) * 128 + tx * 8 + 4] = o1;
    }
    __syncthreads();

    // fused LSTM cell: 64 batch x 32 d outputs = 2048 -> 8 per thread
    #pragma unroll
    for (int r = 0; r < 8; r++) {
        int q = tid + 256 * r;
        int bl = q >> 5, dd = q & 31;
        float gi = sG[bl * 128 + dd];
        float gf = sG[bl * 128 + 32 + dd];
        float gg = sG[bl * 128 + 64 + dd];
        float go = sG[bl * 128 + 96 + dd];
        int idx = (bm0 + bl) * Dn + d0 + dd;
        float c = g_c[idx];
        float cn = sigexact(gf) * c + sigexact(gi) * tanhf(gg);
        float hn = sigexact(go) * tanhf(cn);
        g_c[idx] = cn;
        g_h[idx] = hn;
        hxout[idx] = hn + g_ctx[idx];
    }
}

// ---------------- per-step: logits GEMM + argmax + strided output ----------------
// block = 8 batch rows x 128 V; warp w: rows (w>>2)*4..+3, v = (w&3)*32 + lane.
// No barriers in the K-loop; pwT read coalesced from L1/L2.
__global__ __launch_bounds__(256) void k_logits(int t, const float* __restrict__ projb,
                                                float* __restrict__ out) {
    __shared__ __align__(16) float sHT[512 * 12];   // [k][row], stride 12
    __shared__ float sL[8 * 128];

    int b0 = blockIdx.x * 8;
    int tid = threadIdx.x;
    int lane = tid & 31;
    int wid = tid >> 5;

    // stage h transposed: sHT[k][row]
    {
        int row = wid;
        #pragma unroll
        for (int it = 0; it < 4; it++) {
            int k4 = lane + 32 * it;
            float4 hv = *(const float4*)&g_h[(size_t)(b0 + row) * Dn + k4 * 4];
            sHT[(k4 * 4 + 0) * 12 + row] = hv.x;
            sHT[(k4 * 4 + 1) * 12 + row] = hv.y;
            sHT[(k4 * 4 + 2) * 12 + row] = hv.z;
            sHT[(k4 * 4 + 3) * 12 + row] = hv.w;
        }
    }
    __syncthreads();

    int rbase = (wid >> 2) * 4;
    int v = (wid & 3) * 32 + lane;
    const float* P = g_pwT + v;

    float a0 = 0.f, a1 = 0.f, a2 = 0.f, a3 = 0.f;
    #pragma unroll 4
    for (int k = 0; k < 512; k += 4) {
        float p0 = __ldg(&P[(k + 0) * 128]);
        float p1 = __ldg(&P[(k + 1) * 128]);
        float p2 = __ldg(&P[(k + 2) * 128]);
        float p3 = __ldg(&P[(k + 3) * 128]);
        float4 hA = *(const float4*)&sHT[(k + 0) * 12 + rbase];
        float4 hB = *(const float4*)&sHT[(k + 1) * 12 + rbase];
        float4 hC = *(const float4*)&sHT[(k + 2) * 12 + rbase];
        float4 hD = *(const float4*)&sHT[(k + 3) * 12 + rbase];
        a0 += hA.x * p0 + hB.x * p1 + hC.x * p2 + hD.x * p3;
        a1 += hA.y * p0 + hB.y * p1 + hC.y * p2 + hD.y * p3;
        a2 += hA.z * p0 + hB.z * p1 + hC.z * p2 + hD.z * p3;
        a3 += hA.w * p0 + hB.w * p1 + hC.w * p2 + hD.w * p3;
    }

    float pb = projb[v];
    float lg[4] = {a0 + pb, a1 + pb, a2 + pb, a3 + pb};
    #pragma unroll
    for (int r = 0; r < 4; r++) {
        sL[(rbase + r) * 128 + v] = lg[r];
        out[(size_t)(b0 + rbase + r) * (Vn * Tn) + (size_t)v * Tn + t] = lg[r];
    }
    __syncthreads();

    // argmax per batch row: warp w handles row w (first-max tiebreak)
    int w = wid;
    float best = sL[w * 128 + lane];
    int bidx = lane;
    #pragma unroll
    for (int off = 32; off < 128; off += 32) {
        float vv = sL[w * 128 + lane + off];
        if (vv > best) { best = vv; bidx = lane + off; }
    }
    #pragma unroll
    for (int s = 16; s > 0; s >>= 1) {
        float ov = __shfl_down_sync(0xffffffffu, best, s);
        int oi = __shfl_down_sync(0xffffffffu, bidx, s);
        if (ov > best || (ov == best && oi < bidx)) { best = ov; bidx = oi; }
    }
    if (lane == 0) g_token[b0 + w] = bidx;
}

// ---------------- launch ----------------
extern "C" void kernel_launch(void* const* d_in, const int* in_sizes, int n_in,
                              void* d_out, int out_size) {
    const float* fm     = (const float*)d_in[0];
    const float* pooled = (const float*)d_in[1];
    const float* gamma  = (const float*)d_in[2];
    const float* beta   = (const float*)d_in[3];
    const float* Wih    = (const float*)d_in[4];
    const float* Whh    = (const float*)d_in[5];
    const float* bih    = (const float*)d_in[6];
    const float* bhh    = (const float*)d_in[7];
    const float* emb    = (const float*)d_in[8];
    const float* attnw  = (const float*)d_in[9];
    // d_in[10] = attn_b: cancels in softmax (constant over the axis)
    const float* projw  = (const float*)d_in[11];
    const float* projb  = (const float*)d_in[12];
    const int*   sos    = (const int*)d_in[13];
    float* out = (float*)d_out;

    const int dynBytes = (25088 + 512) * 4;
    cudaFuncSetAttribute(k_init, cudaFuncAttributeMaxDynamicSharedMemorySize, dynBytes);

    k_init<<<Bn, 256, dynBytes>>>(fm, pooled, gamma, beta, attnw, sos);
    k_e2<<<dim3(32, 2), 256>>>(emb, Wih, bih, bhh);
    k_tw<<<256, 256>>>(projw);

    for (int t = 0; t < Tn; t++) {
        k_gates<<<dim3(16, 16), 256>>>(t & 1, Whh);
        k_logits<<<128, 256>>>(t, projb, out);
    }
}

// round 5
// speedup vs baseline: 2.1016x; 2.1016x over previous
#include <cuda_runtime.h>
#include <cuda_fp16.h>
#include <math.h>

#define Bn 1024
#define Dn 512
#define Vn 128
#define Tn 201

// ---------------- device scratch ----------------
__device__ float  g_h[Bn * Dn];            // h_t (read by logits)
__device__ float  g_c[Bn * Dn];
__device__ float  g_ctx[Bn * Dn];
__device__ __half g_Ah[2][Bn * Dn];        // ping-pong hx hi-limb
__device__ __half g_Al[2][Bn * Dn];        // ping-pong hx lo-limb
__device__ __half g_Bh[4 * Dn * Dn];       // W_hh hi-limb [2048x512]
__device__ __half g_Bl[4 * Dn * Dn];       // W_hh lo-limb
__device__ float  g_E2[Vn * 4 * Dn];       // embed @ W_ih^T + b_ih + b_hh
__device__ float  g_pwT[Dn * Vn];          // proj_w transposed [K][V]
__device__ int    g_token[Bn];

__device__ __forceinline__ float sigexact(float x) {
    return 1.f / (1.f + expf(-x));
}
__device__ __forceinline__ void splitf(float x, __half& hi, __half& lo) {
    hi = __float2half_rn(x);
    lo = __float2half_rn(x - __half2float(hi));
}

// ---------------- mma / ldmatrix wrappers ----------------
__device__ __forceinline__ void mma16816(float* c, const unsigned* a, const unsigned* b) {
    asm volatile(
        "mma.sync.aligned.m16n8k16.row.col.f32.f16.f16.f32 "
        "{%0,%1,%2,%3}, {%4,%5,%6,%7}, {%8,%9}, {%0,%1,%2,%3};"
        : "+f"(c[0]), "+f"(c[1]), "+f"(c[2]), "+f"(c[3])
        : "r"(a[0]), "r"(a[1]), "r"(a[2]), "r"(a[3]), "r"(b[0]), "r"(b[1]));
}
__device__ __forceinline__ void ldm4(unsigned* r, unsigned addr) {
    asm volatile("ldmatrix.sync.aligned.m8n8.x4.shared.b16 {%0,%1,%2,%3}, [%4];"
        : "=r"(r[0]), "=r"(r[1]), "=r"(r[2]), "=r"(r[3]) : "r"(addr));
}

// ---------------- P1: layernorm(h0) + attention context + init ----------------
__global__ void k_init(const float* __restrict__ fm, const float* __restrict__ pooled,
                       const float* __restrict__ gamma, const float* __restrict__ beta,
                       const float* __restrict__ attnw, const int* __restrict__ sos) {
    extern __shared__ float dyn[];
    float* sfm = dyn;            // 25088 floats
    float* swf = dyn + 25088;    // 512 floats
    __shared__ float red[256];
    __shared__ float saw[64];
    __shared__ float sstat[2];
    __shared__ float sh0[512];

    int b = blockIdx.x;
    int tid = threadIdx.x;

    const float4* fmb = (const float4*)(fm + (size_t)b * 25088);
    for (int i = tid; i < 6272; i += 256) ((float4*)sfm)[i] = fmb[i];
    for (int i = tid; i < 512; i += 256) swf[i] = attnw[i];

    float x0 = pooled[b * Dn + tid];
    float x1 = pooled[b * Dn + 256 + tid];
    red[tid] = x0 + x1;
    __syncthreads();
    for (int s = 128; s > 0; s >>= 1) {
        if (tid < s) red[tid] += red[tid + s];
        __syncthreads();
    }
    if (tid == 0) sstat[0] = red[0] * (1.0f / Dn);
    __syncthreads();
    float mu = sstat[0];
    float d0 = x0 - mu, d1 = x1 - mu;
    red[tid] = d0 * d0 + d1 * d1;
    __syncthreads();
    for (int s = 128; s > 0; s >>= 1) {
        if (tid < s) red[tid] += red[tid + s];
        __syncthreads();
    }
    if (tid == 0) sstat[1] = rsqrtf(red[0] * (1.0f / Dn) + 1e-5f);
    __syncthreads();
    float rs = sstat[1];
    sh0[tid]       = d0 * rs * gamma[tid]       + beta[tid];
    sh0[256 + tid] = d1 * rs * gamma[256 + tid] + beta[256 + tid];

    if (tid < 49) {
        float sc = 0.f;
        #pragma unroll 8
        for (int d = 0; d < 512; d++) sc += sfm[d * 49 + tid] * swf[d];
        saw[tid] = sc;
    }
    __syncthreads();
    if (tid == 0) {
        float mx = -1e30f;
        for (int p = 0; p < 49; p++) mx = fmaxf(mx, saw[p]);
        float sm = 0.f;
        for (int p = 0; p < 49; p++) { float e = expf(saw[p] - mx); saw[p] = e; sm += e; }
        sstat[0] = 1.0f / sm;
    }
    __syncthreads();
    float inv = sstat[0];

    for (int d = tid; d < 512; d += 256) {
        float acc = 0.f;
        #pragma unroll
        for (int p = 0; p < 49; p++) acc += saw[p] * sfm[d * 49 + p];
        float ctx = acc * inv;
        int idx = b * Dn + d;
        g_ctx[idx] = ctx;
        g_c[idx] = 0.f;
        float hx = ctx + sh0[d];
        __half hi, lo;
        splitf(hx, hi, lo);
        g_Ah[0][idx] = hi;
        g_Al[0][idx] = lo;
    }
    if (tid == 0) g_token[b] = *sos;
}

// ---------------- one-time: split W_hh into f16 limbs ----------------
__global__ void k_splitW(const float* __restrict__ W) {
    int idx = blockIdx.x * 256 + threadIdx.x;   // 1048576 total
    float x = W[idx];
    __half hi, lo;
    splitf(x, hi, lo);
    g_Bh[idx] = hi;
    g_Bl[idx] = lo;
}

// ---------------- E2 = embed @ W_ih^T + b_ih + b_hh (one-time) ----------------
__global__ __launch_bounds__(256) void k_e2(const float* __restrict__ emb,
                                            const float* __restrict__ Wih,
                                            const float* __restrict__ bih,
                                            const float* __restrict__ bhh) {
    __shared__ __align__(16) float sA[16 * 68];
    __shared__ __align__(16) float sB[16 * 68];
    int m0 = blockIdx.y * 64;
    int n0 = blockIdx.x * 64;
    int tid = threadIdx.x;
    int tx = tid & 15, ty = tid >> 4;
    int lm = tid >> 2;
    int lk = (tid & 3) * 4;
    const float* Ap = emb + (size_t)(m0 + lm) * Dn + lk;
    const float* Bp = Wih + (size_t)(n0 + lm) * Dn + lk;
    float acc[4][4] = {};
    for (int kt = 0; kt < 512; kt += 16) {
        float4 a = *(const float4*)(Ap + kt);
        float4 bb = *(const float4*)(Bp + kt);
        sA[(lk + 0) * 68 + lm] = a.x;  sA[(lk + 1) * 68 + lm] = a.y;
        sA[(lk + 2) * 68 + lm] = a.z;  sA[(lk + 3) * 68 + lm] = a.w;
        sB[(lk + 0) * 68 + lm] = bb.x; sB[(lk + 1) * 68 + lm] = bb.y;
        sB[(lk + 2) * 68 + lm] = bb.z; sB[(lk + 3) * 68 + lm] = bb.w;
        __syncthreads();
        #pragma unroll
        for (int k = 0; k < 16; k++) {
            float4 av = *(const float4*)&sA[k * 68 + ty * 4];
            float4 bv = *(const float4*)&sB[k * 68 + tx * 4];
            float ar[4] = {av.x, av.y, av.z, av.w};
            float br[4] = {bv.x, bv.y, bv.z, bv.w};
            #pragma unroll
            for (int i = 0; i < 4; i++)
                #pragma unroll
                for (int j = 0; j < 4; j++) acc[i][j] += ar[i] * br[j];
        }
        __syncthreads();
    }
    int gj0 = n0 + tx * 4;
    float4 b1 = *(const float4*)&bih[gj0];
    float4 b2 = *(const float4*)&bhh[gj0];
    #pragma unroll
    for (int i = 0; i < 4; i++) {
        int gv = m0 + ty * 4 + i;
        float4 o;
        o.x = acc[i][0] + b1.x + b2.x;
        o.y = acc[i][1] + b1.y + b2.y;
        o.z = acc[i][2] + b1.z + b2.z;
        o.w = acc[i][3] + b1.w + b2.w;
        *(float4*)&g_E2[(size_t)gv * 2048 + gj0] = o;
    }
}

// ---------------- proj_w transpose (one-time) ----------------
__global__ void k_tw(const float* __restrict__ projw) {
    int idx = blockIdx.x * 256 + threadIdx.x;   // 65536 total
    int vv = idx >> 9;
    int kk = idx & 511;
    g_pwT[kk * 128 + vv] = projw[idx];
}

// ---------------- per-step: gates GEMM (tensor cores, f16 2-limb) + LSTM cell ----
// C = Ah*Bh + Ah*Bl + Al*Bh  (fp32 accum).  Block tile 128(batch) x 128(n),
// n gate-grouped: n = gate*32 + dd, block owns d in [bx*32, bx*32+32).
// 8 warps as 2(m) x 4(n): warp tile 64x32 = 4x4 mma.m16n8k16 tiles.
#define OFF_AH 0
#define OFF_AL 6144
#define OFF_BH 12288
#define OFF_BL 18432
#define SG_STRIDE 132
#define SG_BYTES (128 * SG_STRIDE * 4)

__global__ __launch_bounds__(256, 1) void k_gates(int par) {
    extern __shared__ char sdyn[];
    float* sG = (float*)sdyn;

    const __half* Ahp = g_Ah[par];
    const __half* Alp = g_Al[par];
    __half* AhO = g_Ah[par ^ 1];
    __half* AlO = g_Al[par ^ 1];

    int tid = threadIdx.x;
    int lane = tid & 31;
    int wid = tid >> 5;
    int d0 = blockIdx.x * 32;
    int bm0 = blockIdx.y * 128;

    int m0w = (wid >> 2) * 64;
    int n0w = (wid & 3) * 32;

    unsigned sb = (unsigned)__cvta_generic_to_shared(sdyn);

    // ldmatrix lane addresses (constant across k-iterations)
    unsigned aAH[4], aAL[4], bAH[2], bAL[2];
    #pragma unroll
    for (int mi = 0; mi < 4; mi++) {
        int row = m0w + mi * 16 + ((lane >> 3) & 1) * 8 + (lane & 7);
        unsigned off = (unsigned)(row * 48 + ((lane >> 4) & 1) * 16);
        aAH[mi] = sb + OFF_AH + off;
        aAL[mi] = sb + OFF_AL + off;
    }
    #pragma unroll
    for (int pi = 0; pi < 2; pi++) {
        int row = n0w + pi * 16 + ((lane >> 4) & 1) * 8 + (lane & 7);
        unsigned off = (unsigned)(row * 48 + ((lane >> 3) & 1) * 16);
        bAH[pi] = sb + OFF_BH + off;
        bAL[pi] = sb + OFF_BL + off;
    }

    // staging assignments
    int srow = tid >> 1;            // 0..127
    int shalf = tid & 1;            // 16B half of the 32B row
    const uint4* gAh = (const uint4*)(Ahp + (size_t)(bm0 + srow) * Dn + shalf * 8);
    const uint4* gAl = (const uint4*)(Alp + (size_t)(bm0 + srow) * Dn + shalf * 8);
    int grow = (srow >> 5) * 512 + d0 + (srow & 31);
    const uint4* gBh = (const uint4*)(g_Bh + (size_t)grow * Dn + shalf * 8);
    const uint4* gBl = (const uint4*)(g_Bl + (size_t)grow * Dn + shalf * 8);
    char* stA_h = sdyn + OFF_AH + srow * 48 + shalf * 16;
    char* stA_l = sdyn + OFF_AL + srow * 48 + shalf * 16;
    char* stB_h = sdyn + OFF_BH + srow * 48 + shalf * 16;
    char* stB_l = sdyn + OFF_BL + srow * 48 + shalf * 16;

    float c[4][4][4];
    #pragma unroll
    for (int mi = 0; mi < 4; mi++)
        #pragma unroll
        for (int ni = 0; ni < 4; ni++)
            #pragma unroll
            for (int q = 0; q < 4; q++) c[mi][ni][q] = 0.f;

    for (int kt = 0; kt < 32; kt++) {   // k16 tiles (each 16 f16 = 32B; half = 16B = 8 f16)
        *(uint4*)stA_h = gAh[kt * 2];   // kt*16 f16 = kt*2 uint4
        *(uint4*)stA_l = gAl[kt * 2];
        *(uint4*)stB_h = gBh[kt * 2];
        *(uint4*)stB_l = gBl[kt * 2];
        __syncthreads();

        unsigned AH[4][4], AL[4][4], BH[2][4], BL[2][4];
        #pragma unroll
        for (int mi = 0; mi < 4; mi++) { ldm4(AH[mi], aAH[mi]); ldm4(AL[mi], aAL[mi]); }
        #pragma unroll
        for (int pi = 0; pi < 2; pi++) { ldm4(BH[pi], bAH[pi]); ldm4(BL[pi], bAL[pi]); }

        #pragma unroll
        for (int mi = 0; mi < 4; mi++) {
            #pragma unroll
            for (int ni = 0; ni < 4; ni++) {
                int pair = ni >> 1;
                int bx = (ni & 1) * 2;
                mma16816(c[mi][ni], AH[mi], &BH[pair][bx]);
                mma16816(c[mi][ni], AH[mi], &BL[pair][bx]);
                mma16816(c[mi][ni], AL[mi], &BH[pair][bx]);
            }
        }
        __syncthreads();
    }

    // write fragments to sG (padded stride kills bank conflicts)
    int g = lane >> 2, tg = lane & 3;
    #pragma unroll
    for (int mi = 0; mi < 4; mi++) {
        #pragma unroll
        for (int ni = 0; ni < 4; ni++) {
            int row = m0w + mi * 16 + g;
            int col = n0w + ni * 8 + tg * 2;
            *(float2*)&sG[row * SG_STRIDE + col]       = make_float2(c[mi][ni][0], c[mi][ni][1]);
            *(float2*)&sG[(row + 8) * SG_STRIDE + col] = make_float2(c[mi][ni][2], c[mi][ni][3]);
        }
    }
    __syncthreads();

    // fused LSTM cell: 128 batch x 32 d = 4096 outputs -> 16 per thread
    #pragma unroll
    for (int r = 0; r < 16; r++) {
        int q = tid + 256 * r;
        int bl = q >> 5, dd = q & 31;
        int gb = bm0 + bl;
        int tok = g_token[gb];
        const float* E = g_E2 + (size_t)tok * 2048 + d0 + dd;
        float gi = sG[bl * SG_STRIDE + dd]      + E[0];
        float gf = sG[bl * SG_STRIDE + 32 + dd] + E[512];
        float gg = sG[bl * SG_STRIDE + 64 + dd] + E[1024];
        float go = sG[bl * SG_STRIDE + 96 + dd] + E[1536];
        int idx = gb * Dn + d0 + dd;
        float cold = g_c[idx];
        float cn = sigexact(gf) * cold + sigexact(gi) * tanhf(gg);
        float hn = sigexact(go) * tanhf(cn);
        g_c[idx] = cn;
        g_h[idx] = hn;
        float hx = hn + g_ctx[idx];
        __half hi, lo;
        splitf(hx, hi, lo);
        AhO[idx] = hi;
        AlO[idx] = lo;
    }
}

// ---------------- per-step: logits GEMM + argmax + strided output ----------------
__global__ __launch_bounds__(256) void k_logits(int t, const float* __restrict__ projb,
                                                float* __restrict__ out) {
    __shared__ __align__(16) float sHT[512 * 12];   // [k][row], stride 12
    __shared__ float sL[8 * 128];

    int b0 = blockIdx.x * 8;
    int tid = threadIdx.x;
    int lane = tid & 31;
    int wid = tid >> 5;

    {
        int row = wid;
        #pragma unroll
        for (int it = 0; it < 4; it++) {
            int k4 = lane + 32 * it;
            float4 hv = *(const float4*)&g_h[(size_t)(b0 + row) * Dn + k4 * 4];
            sHT[(k4 * 4 + 0) * 12 + row] = hv.x;
            sHT[(k4 * 4 + 1) * 12 + row] = hv.y;
            sHT[(k4 * 4 + 2) * 12 + row] = hv.z;
            sHT[(k4 * 4 + 3) * 12 + row] = hv.w;
        }
    }
    __syncthreads();

    int rbase = (wid >> 2) * 4;
    int v = (wid & 3) * 32 + lane;
    const float* P = g_pwT + v;

    float a0 = 0.f, a1 = 0.f, a2 = 0.f, a3 = 0.f;
    #pragma unroll 4
    for (int k = 0; k < 512; k += 4) {
        float p0 = __ldg(&P[(k + 0) * 128]);
        float p1 = __ldg(&P[(k + 1) * 128]);
        float p2 = __ldg(&P[(k + 2) * 128]);
        float p3 = __ldg(&P[(k + 3) * 128]);
        float4 hA = *(const float4*)&sHT[(k + 0) * 12 + rbase];
        float4 hB = *(const float4*)&sHT[(k + 1) * 12 + rbase];
        float4 hC = *(const float4*)&sHT[(k + 2) * 12 + rbase];
        float4 hD = *(const float4*)&sHT[(k + 3) * 12 + rbase];
        a0 += hA.x * p0 + hB.x * p1 + hC.x * p2 + hD.x * p3;
        a1 += hA.y * p0 + hB.y * p1 + hC.y * p2 + hD.y * p3;
        a2 += hA.z * p0 + hB.z * p1 + hC.z * p2 + hD.z * p3;
        a3 += hA.w * p0 + hB.w * p1 + hC.w * p2 + hD.w * p3;
    }

    float pb = projb[v];
    float lg[4] = {a0 + pb, a1 + pb, a2 + pb, a3 + pb};
    #pragma unroll
    for (int r = 0; r < 4; r++) {
        sL[(rbase + r) * 128 + v] = lg[r];
        out[(size_t)(b0 + rbase + r) * (Vn * Tn) + (size_t)v * Tn + t] = lg[r];
    }
    __syncthreads();

    int w = wid;
    float best = sL[w * 128 + lane];
    int bidx = lane;
    #pragma unroll
    for (int off = 32; off < 128; off += 32) {
        float vv = sL[w * 128 + lane + off];
        if (vv > best) { best = vv; bidx = lane + off; }
    }
    #pragma unroll
    for (int s = 16; s > 0; s >>= 1) {
        float ov = __shfl_down_sync(0xffffffffu, best, s);
        int oi = __shfl_down_sync(0xffffffffu, bidx, s);
        if (ov > best || (ov == best && oi < bidx)) { best = ov; bidx = oi; }
    }
    if (lane == 0) g_token[b0 + w] = bidx;
}

// ---------------- launch ----------------
extern "C" void kernel_launch(void* const* d_in, const int* in_sizes, int n_in,
                              void* d_out, int out_size) {
    const float* fm     = (const float*)d_in[0];
    const float* pooled = (const float*)d_in[1];
    const float* gamma  = (const float*)d_in[2];
    const float* beta   = (const float*)d_in[3];
    const float* Wih    = (const float*)d_in[4];
    const float* Whh    = (const float*)d_in[5];
    const float* bih    = (const float*)d_in[6];
    const float* bhh    = (const float*)d_in[7];
    const float* emb    = (const float*)d_in[8];
    const float* attnw  = (const float*)d_in[9];
    // d_in[10] = attn_b: cancels in softmax (constant over the axis)
    const float* projw  = (const float*)d_in[11];
    const float* projb  = (const float*)d_in[12];
    const int*   sos    = (const int*)d_in[13];
    float* out = (float*)d_out;

    const int dynBytes = (25088 + 512) * 4;
    cudaFuncSetAttribute(k_init, cudaFuncAttributeMaxDynamicSharedMemorySize, dynBytes);
    cudaFuncSetAttribute(k_gates, cudaFuncAttributeMaxDynamicSharedMemorySize, SG_BYTES);

    k_init<<<Bn, 256, dynBytes>>>(fm, pooled, gamma, beta, attnw, sos);
    k_splitW<<<4096, 256>>>(Whh);
    k_e2<<<dim3(32, 2), 256>>>(emb, Wih, bih, bhh);
    k_tw<<<256, 256>>>(projw);

    for (int t = 0; t < Tn; t++) {
        k_gates<<<dim3(16, 8), 256, SG_BYTES>>>(t & 1);
        k_logits<<<128, 256>>>(t, projb, out);
    }
}

// round 6
// speedup vs baseline: 2.8822x; 1.3714x over previous
#include <cuda_runtime.h>
#include <cuda_fp16.h>
#include <math.h>

#define Bn 1024
#define Dn 512
#define Vn 128
#define Tn 201

// ---------------- device scratch ----------------
__device__ float  g_h[Bn * Dn];            // h_t (read by logits)
__device__ float  g_c[Bn * Dn];
__device__ float  g_ctx[Bn * Dn];
__device__ __half g_Ah[2][Bn * Dn];        // ping-pong hx hi-limb
__device__ __half g_Al[2][Bn * Dn];        // ping-pong hx lo-limb
__device__ __half g_Bh[4 * Dn * Dn];       // W_hh hi-limb [2048x512]
__device__ __half g_Bl[4 * Dn * Dn];       // W_hh lo-limb
__device__ float  g_E2[Vn * 4 * Dn];       // embed @ W_ih^T + b_ih + b_hh
__device__ float  g_pwT[Dn * Vn];          // proj_w transposed [K][V]
__device__ int    g_token[Bn];

__device__ __forceinline__ float sigexact(float x) {
    return 1.f / (1.f + expf(-x));
}
__device__ __forceinline__ void splitf(float x, __half& hi, __half& lo) {
    hi = __float2half_rn(x);
    lo = __float2half_rn(x - __half2float(hi));
}

// ---------------- mma / ldmatrix / cp.async wrappers ----------------
__device__ __forceinline__ void mma16816(float* c, const unsigned* a, const unsigned* b) {
    asm volatile(
        "mma.sync.aligned.m16n8k16.row.col.f32.f16.f16.f32 "
        "{%0,%1,%2,%3}, {%4,%5,%6,%7}, {%8,%9}, {%0,%1,%2,%3};"
        : "+f"(c[0]), "+f"(c[1]), "+f"(c[2]), "+f"(c[3])
        : "r"(a[0]), "r"(a[1]), "r"(a[2]), "r"(a[3]), "r"(b[0]), "r"(b[1]));
}
__device__ __forceinline__ void ldm4(unsigned* r, unsigned addr) {
    asm volatile("ldmatrix.sync.aligned.m8n8.x4.shared.b16 {%0,%1,%2,%3}, [%4];"
        : "=r"(r[0]), "=r"(r[1]), "=r"(r[2]), "=r"(r[3]) : "r"(addr));
}
__device__ __forceinline__ void cpasync16(unsigned dst, const void* src) {
    asm volatile("cp.async.ca.shared.global [%0], [%1], 16;" :: "r"(dst), "l"(src));
}
#define CP_COMMIT() asm volatile("cp.async.commit_group;")
#define CP_WAIT2()  asm volatile("cp.async.wait_group 2;")

// ---------------- P1: layernorm(h0) + attention context + init ----------------
__global__ void k_init(const float* __restrict__ fm, const float* __restrict__ pooled,
                       const float* __restrict__ gamma, const float* __restrict__ beta,
                       const float* __restrict__ attnw, const int* __restrict__ sos) {
    extern __shared__ float dyn[];
    float* sfm = dyn;            // 25088 floats
    float* swf = dyn + 25088;    // 512 floats
    __shared__ float red[256];
    __shared__ float saw[64];
    __shared__ float sstat[2];
    __shared__ float sh0[512];

    int b = blockIdx.x;
    int tid = threadIdx.x;

    const float4* fmb = (const float4*)(fm + (size_t)b * 25088);
    for (int i = tid; i < 6272; i += 256) ((float4*)sfm)[i] = fmb[i];
    for (int i = tid; i < 512; i += 256) swf[i] = attnw[i];

    float x0 = pooled[b * Dn + tid];
    float x1 = pooled[b * Dn + 256 + tid];
    red[tid] = x0 + x1;
    __syncthreads();
    for (int s = 128; s > 0; s >>= 1) {
        if (tid < s) red[tid] += red[tid + s];
        __syncthreads();
    }
    if (tid == 0) sstat[0] = red[0] * (1.0f / Dn);
    __syncthreads();
    float mu = sstat[0];
    float d0 = x0 - mu, d1 = x1 - mu;
    red[tid] = d0 * d0 + d1 * d1;
    __syncthreads();
    for (int s = 128; s > 0; s >>= 1) {
        if (tid < s) red[tid] += red[tid + s];
        __syncthreads();
    }
    if (tid == 0) sstat[1] = rsqrtf(red[0] * (1.0f / Dn) + 1e-5f);
    __syncthreads();
    float rs = sstat[1];
    sh0[tid]       = d0 * rs * gamma[tid]       + beta[tid];
    sh0[256 + tid] = d1 * rs * gamma[256 + tid] + beta[256 + tid];

    if (tid < 49) {
        float sc = 0.f;
        #pragma unroll 8
        for (int d = 0; d < 512; d++) sc += sfm[d * 49 + tid] * swf[d];
        saw[tid] = sc;
    }
    __syncthreads();
    if (tid == 0) {
        float mx = -1e30f;
        for (int p = 0; p < 49; p++) mx = fmaxf(mx, saw[p]);
        float sm = 0.f;
        for (int p = 0; p < 49; p++) { float e = expf(saw[p] - mx); saw[p] = e; sm += e; }
        sstat[0] = 1.0f / sm;
    }
    __syncthreads();
    float inv = sstat[0];

    for (int d = tid; d < 512; d += 256) {
        float acc = 0.f;
        #pragma unroll
        for (int p = 0; p < 49; p++) acc += saw[p] * sfm[d * 49 + p];
        float ctx = acc * inv;
        int idx = b * Dn + d;
        g_ctx[idx] = ctx;
        g_c[idx] = 0.f;
        float hx = ctx + sh0[d];
        __half hi, lo;
        splitf(hx, hi, lo);
        g_Ah[0][idx] = hi;
        g_Al[0][idx] = lo;
    }
    if (tid == 0) g_token[b] = *sos;
}

// ---------------- one-time: split W_hh into f16 limbs ----------------
__global__ void k_splitW(const float* __restrict__ W) {
    int idx = blockIdx.x * 256 + threadIdx.x;   // 1048576 total
    float x = W[idx];
    __half hi, lo;
    splitf(x, hi, lo);
    g_Bh[idx] = hi;
    g_Bl[idx] = lo;
}

// ---------------- E2 = embed @ W_ih^T + b_ih + b_hh (one-time) ----------------
__global__ __launch_bounds__(256) void k_e2(const float* __restrict__ emb,
                                            const float* __restrict__ Wih,
                                            const float* __restrict__ bih,
                                            const float* __restrict__ bhh) {
    __shared__ __align__(16) float sA[16 * 68];
    __shared__ __align__(16) float sB[16 * 68];
    int m0 = blockIdx.y * 64;
    int n0 = blockIdx.x * 64;
    int tid = threadIdx.x;
    int tx = tid & 15, ty = tid >> 4;
    int lm = tid >> 2;
    int lk = (tid & 3) * 4;
    const float* Ap = emb + (size_t)(m0 + lm) * Dn + lk;
    const float* Bp = Wih + (size_t)(n0 + lm) * Dn + lk;
    float acc[4][4] = {};
    for (int kt = 0; kt < 512; kt += 16) {
        float4 a = *(const float4*)(Ap + kt);
        float4 bb = *(const float4*)(Bp + kt);
        sA[(lk + 0) * 68 + lm] = a.x;  sA[(lk + 1) * 68 + lm] = a.y;
        sA[(lk + 2) * 68 + lm] = a.z;  sA[(lk + 3) * 68 + lm] = a.w;
        sB[(lk + 0) * 68 + lm] = bb.x; sB[(lk + 1) * 68 + lm] = bb.y;
        sB[(lk + 2) * 68 + lm] = bb.z; sB[(lk + 3) * 68 + lm] = bb.w;
        __syncthreads();
        #pragma unroll
        for (int k = 0; k < 16; k++) {
            float4 av = *(const float4*)&sA[k * 68 + ty * 4];
            float4 bv = *(const float4*)&sB[k * 68 + tx * 4];
            float ar[4] = {av.x, av.y, av.z, av.w};
            float br[4] = {bv.x, bv.y, bv.z, bv.w};
            #pragma unroll
            for (int i = 0; i < 4; i++)
                #pragma unroll
                for (int j = 0; j < 4; j++) acc[i][j] += ar[i] * br[j];
        }
        __syncthreads();
    }
    int gj0 = n0 + tx * 4;
    float4 b1 = *(const float4*)&bih[gj0];
    float4 b2 = *(const float4*)&bhh[gj0];
    #pragma unroll
    for (int i = 0; i < 4; i++) {
        int gv = m0 + ty * 4 + i;
        float4 o;
        o.x = acc[i][0] + b1.x + b2.x;
        o.y = acc[i][1] + b1.y + b2.y;
        o.z = acc[i][2] + b1.z + b2.z;
        o.w = acc[i][3] + b1.w + b2.w;
        *(float4*)&g_E2[(size_t)gv * 2048 + gj0] = o;
    }
}

// ---------------- proj_w transpose (one-time) ----------------
__global__ void k_tw(const float* __restrict__ projw) {
    int idx = blockIdx.x * 256 + threadIdx.x;   // 65536 total
    int vv = idx >> 9;
    int kk = idx & 511;
    g_pwT[kk * 128 + vv] = projw[idx];
}

// ---------------- per-step: gates GEMM (tensor cores, f16 2-limb) + LSTM cell ----
// C = Ah*Bh + Ah*Bl + Al*Bh (fp32 accum). Block: 128(batch) x 128(n).
// N mapping is gate-interleaved: local col nl -> gate=(nl>>3)&3, dloc=(nl>>5)*8+(nl&7),
// so a warp's four n8 MMA tiles are the FOUR GATES of the same 8 d's ->
// LSTM cell entirely in registers, no smem exchange.
// 4-stage cp.async pipeline, one __syncthreads per k16 iteration.
#define ST_ROW 48
#define OFF_AH 0
#define OFF_AL 6144
#define OFF_BH 12288
#define OFF_BL 18432
#define STAGE_BYTES 24576
#define SMEM_GATES (STAGE_BYTES * 4)

__global__ __launch_bounds__(256, 1) void k_gates(int par) {
    extern __shared__ char sdyn[];
    const __half* Ahp = g_Ah[par];
    const __half* Alp = g_Al[par];
    __half* AhO = g_Ah[par ^ 1];
    __half* AlO = g_Al[par ^ 1];

    int tid = threadIdx.x;
    int lane = tid & 31;
    int wid = tid >> 5;
    int d0 = blockIdx.x * 32;
    int bm0 = blockIdx.y * 128;
    int m0w = (wid >> 2) * 64;
    int wn = wid & 3;               // 8-wide d-subrange within block's 32 d's

    unsigned sb = (unsigned)__cvta_generic_to_shared(sdyn);

    // ldmatrix lane base addresses (stage 0)
    unsigned aAH[4], aAL[4], bAH[2], bAL[2];
    #pragma unroll
    for (int mi = 0; mi < 4; mi++) {
        int row = m0w + mi * 16 + ((lane >> 3) & 1) * 8 + (lane & 7);
        unsigned off = (unsigned)(row * ST_ROW + ((lane >> 4) & 1) * 16);
        aAH[mi] = sb + OFF_AH + off;
        aAL[mi] = sb + OFF_AL + off;
    }
    #pragma unroll
    for (int pi = 0; pi < 2; pi++) {
        int row = wn * 32 + pi * 16 + ((lane >> 4) & 1) * 8 + (lane & 7);
        unsigned off = (unsigned)(row * ST_ROW + ((lane >> 3) & 1) * 16);
        bAH[pi] = sb + OFF_BH + off;
        bAL[pi] = sb + OFF_BL + off;
    }

    // staging: each thread copies 16B per array per stage
    int srow = tid >> 1, shalf = tid & 1;
    const char* gAh = (const char*)(Ahp + (size_t)(bm0 + srow) * Dn + shalf * 8);
    const char* gAl = (const char*)(Alp + (size_t)(bm0 + srow) * Dn + shalf * 8);
    int grow = ((srow >> 3) & 3) * 512 + d0 + (srow >> 5) * 8 + (srow & 7);
    const char* gBh = (const char*)(g_Bh + (size_t)grow * Dn + shalf * 8);
    const char* gBl = (const char*)(g_Bl + (size_t)grow * Dn + shalf * 8);
    unsigned stOff = (unsigned)(srow * ST_ROW + shalf * 16);

    float c[4][4][4];
    #pragma unroll
    for (int mi = 0; mi < 4; mi++)
        #pragma unroll
        for (int ni = 0; ni < 4; ni++)
            #pragma unroll
            for (int q = 0; q < 4; q++) c[mi][ni][q] = 0.f;

    // prefetch stages 0..2
    #pragma unroll
    for (int s = 0; s < 3; s++) {
        unsigned so = sb + (unsigned)(s * STAGE_BYTES);
        int go = s * 32;
        cpasync16(so + OFF_AH + stOff, gAh + go);
        cpasync16(so + OFF_AL + stOff, gAl + go);
        cpasync16(so + OFF_BH + stOff, gBh + go);
        cpasync16(so + OFF_BL + stOff, gBl + go);
        CP_COMMIT();
    }

    for (int kt = 0; kt < 32; kt++) {
        CP_WAIT2();
        __syncthreads();
        unsigned so = (unsigned)((kt & 3) * STAGE_BYTES);

        unsigned AH[4][4], AL[4][4], BH[2][4], BL[2][4];
        #pragma unroll
        for (int mi = 0; mi < 4; mi++) { ldm4(AH[mi], aAH[mi] + so); ldm4(AL[mi], aAL[mi] + so); }
        #pragma unroll
        for (int pi = 0; pi < 2; pi++) { ldm4(BH[pi], bAH[pi] + so); ldm4(BL[pi], bAL[pi] + so); }

        // issue stage kt+3 while tensor cores crunch this one
        if (kt + 3 < 32) {
            unsigned sw = sb + (unsigned)(((kt + 3) & 3) * STAGE_BYTES);
            int go = (kt + 3) * 32;
            cpasync16(sw + OFF_AH + stOff, gAh + go);
            cpasync16(sw + OFF_AL + stOff, gAl + go);
            cpasync16(sw + OFF_BH + stOff, gBh + go);
            cpasync16(sw + OFF_BL + stOff, gBl + go);
        }
        CP_COMMIT();

        #pragma unroll
        for (int mi = 0; mi < 4; mi++) {
            #pragma unroll
            for (int ni = 0; ni < 4; ni++) {
                int pair = ni >> 1;
                int bx = (ni & 1) * 2;
                mma16816(c[mi][ni], AH[mi], &BH[pair][bx]);
                mma16816(c[mi][ni], AH[mi], &BL[pair][bx]);
                mma16816(c[mi][ni], AL[mi], &BH[pair][bx]);
            }
        }
    }

    // register LSTM epilogue: c[mi][gate][frag] holds all 4 gates of each element
    int g = lane >> 2, tg = lane & 3;
    int ddb = wn * 8 + tg * 2;
    #pragma unroll
    for (int mi = 0; mi < 4; mi++) {
        #pragma unroll
        for (int q = 0; q < 2; q++) {
            int row = bm0 + m0w + mi * 16 + g + q * 8;
            int tok = g_token[row];
            const float* E = g_E2 + (size_t)tok * 2048 + d0 + ddb;
            float2 ei = *(const float2*)(E);
            float2 ef = *(const float2*)(E + 512);
            float2 eg = *(const float2*)(E + 1024);
            float2 eo = *(const float2*)(E + 1536);
            int idx = row * Dn + d0 + ddb;
            float2 cold = *(const float2*)&g_c[idx];
            float2 ctx = *(const float2*)&g_ctx[idx];

            float gi = c[mi][0][q * 2 + 0] + ei.x;
            float gf = c[mi][1][q * 2 + 0] + ef.x;
            float gg = c[mi][2][q * 2 + 0] + eg.x;
            float go = c[mi][3][q * 2 + 0] + eo.x;
            float cn0 = sigexact(gf) * cold.x + sigexact(gi) * tanhf(gg);
            float hn0 = sigexact(go) * tanhf(cn0);

            gi = c[mi][0][q * 2 + 1] + ei.y;
            gf = c[mi][1][q * 2 + 1] + ef.y;
            gg = c[mi][2][q * 2 + 1] + eg.y;
            go = c[mi][3][q * 2 + 1] + eo.y;
            float cn1 = sigexact(gf) * cold.y + sigexact(gi) * tanhf(gg);
            float hn1 = sigexact(go) * tanhf(cn1);

            *(float2*)&g_c[idx] = make_float2(cn0, cn1);
            *(float2*)&g_h[idx] = make_float2(hn0, hn1);
            float hx0 = hn0 + ctx.x;
            float hx1 = hn1 + ctx.y;
            __half h0h, h0l, h1h, h1l;
            splitf(hx0, h0h, h0l);
            splitf(hx1, h1h, h1l);
            *(__half2*)&AhO[idx] = __halves2half2(h0h, h1h);
            *(__half2*)&AlO[idx] = __halves2half2(h0l, h1l);
        }
    }
}

// ---------------- per-step: logits GEMM + argmax + strided output ----------------
__global__ __launch_bounds__(256) void k_logits(int t, const float* __restrict__ projb,
                                                float* __restrict__ out) {
    __shared__ __align__(16) float sHT[512 * 12];   // [k][row], stride 12
    __shared__ float sL[8 * 128];

    int b0 = blockIdx.x * 8;
    int tid = threadIdx.x;
    int lane = tid & 31;
    int wid = tid >> 5;

    {
        int row = wid;
        #pragma unroll
        for (int it = 0; it < 4; it++) {
            int k4 = lane + 32 * it;
            float4 hv = *(const float4*)&g_h[(size_t)(b0 + row) * Dn + k4 * 4];
            sHT[(k4 * 4 + 0) * 12 + row] = hv.x;
            sHT[(k4 * 4 + 1) * 12 + row] = hv.y;
            sHT[(k4 * 4 + 2) * 12 + row] = hv.z;
            sHT[(k4 * 4 + 3) * 12 + row] = hv.w;
        }
    }
    __syncthreads();

    int rbase = (wid >> 2) * 4;
    int v = (wid & 3) * 32 + lane;
    const float* P = g_pwT + v;

    float a0 = 0.f, a1 = 0.f, a2 = 0.f, a3 = 0.f;
    #pragma unroll 4
    for (int k = 0; k < 512; k += 4) {
        float p0 = __ldg(&P[(k + 0) * 128]);
        float p1 = __ldg(&P[(k + 1) * 128]);
        float p2 = __ldg(&P[(k + 2) * 128]);
        float p3 = __ldg(&P[(k + 3) * 128]);
        float4 hA = *(const float4*)&sHT[(k + 0) * 12 + rbase];
        float4 hB = *(const float4*)&sHT[(k + 1) * 12 + rbase];
        float4 hC = *(const float4*)&sHT[(k + 2) * 12 + rbase];
        float4 hD = *(const float4*)&sHT[(k + 3) * 12 + rbase];
        a0 += hA.x * p0 + hB.x * p1 + hC.x * p2 + hD.x * p3;
        a1 += hA.y * p0 + hB.y * p1 + hC.y * p2 + hD.y * p3;
        a2 += hA.z * p0 + hB.z * p1 + hC.z * p2 + hD.z * p3;
        a3 += hA.w * p0 + hB.w * p1 + hC.w * p2 + hD.w * p3;
    }

    float pb = projb[v];
    float lg[4] = {a0 + pb, a1 + pb, a2 + pb, a3 + pb};
    #pragma unroll
    for (int r = 0; r < 4; r++) {
        sL[(rbase + r) * 128 + v] = lg[r];
        out[(size_t)(b0 + rbase + r) * (Vn * Tn) + (size_t)v * Tn + t] = lg[r];
    }
    __syncthreads();

    int w = wid;
    float best = sL[w * 128 + lane];
    int bidx = lane;
    #pragma unroll
    for (int off = 32; off < 128; off += 32) {
        float vv = sL[w * 128 + lane + off];
        if (vv > best) { best = vv; bidx = lane + off; }
    }
    #pragma unroll
    for (int s = 16; s > 0; s >>= 1) {
        float ov = __shfl_down_sync(0xffffffffu, best, s);
        int oi = __shfl_down_sync(0xffffffffu, bidx, s);
        if (ov > best || (ov == best && oi < bidx)) { best = ov; bidx = oi; }
    }
    if (lane == 0) g_token[b0 + w] = bidx;
}

// ---------------- launch ----------------
extern "C" void kernel_launch(void* const* d_in, const int* in_sizes, int n_in,
                              void* d_out, int out_size) {
    const float* fm     = (const float*)d_in[0];
    const float* pooled = (const float*)d_in[1];
    const float* gamma  = (const float*)d_in[2];
    const float* beta   = (const float*)d_in[3];
    const float* Wih    = (const float*)d_in[4];
    const float* Whh    = (const float*)d_in[5];
    const float* bih    = (const float*)d_in[6];
    const float* bhh    = (const float*)d_in[7];
    const float* emb    = (const float*)d_in[8];
    const float* attnw  = (const float*)d_in[9];
    // d_in[10] = attn_b: cancels in softmax (constant over the axis)
    const float* projw  = (const float*)d_in[11];
    const float* projb  = (const float*)d_in[12];
    const int*   sos    = (const int*)d_in[13];
    float* out = (float*)d_out;

    const int dynBytes = (25088 + 512) * 4;
    cudaFuncSetAttribute(k_init, cudaFuncAttributeMaxDynamicSharedMemorySize, dynBytes);
    cudaFuncSetAttribute(k_gates, cudaFuncAttributeMaxDynamicSharedMemorySize, SMEM_GATES);

    k_init<<<Bn, 256, dynBytes>>>(fm, pooled, gamma, beta, attnw, sos);
    k_splitW<<<4096, 256>>>(Whh);
    k_e2<<<dim3(32, 2), 256>>>(emb, Wih, bih, bhh);
    k_tw<<<256, 256>>>(projw);

    for (int t = 0; t < Tn; t++) {
        k_gates<<<dim3(16, 8), 256, SMEM_GATES>>>(t & 1);
        k_logits<<<128, 256>>>(t, projb, out);
    }
}

// round 8
// speedup vs baseline: 2.8823x; 1.0000x over previous
#include <cuda_runtime.h>
#include <cuda_fp16.h>
#include <math.h>

#define Bn 1024
#define Dn 512
#define Vn 128
#define Tn 201

// ---------------- device scratch ----------------
__device__ float  g_h[Bn * Dn];            // h_t (read by logits)
__device__ float  g_c[Bn * Dn];
__device__ float  g_ctx[Bn * Dn];
__device__ __half g_Ah[2][Bn * Dn];        // ping-pong hx hi-limb
__device__ __half g_Al[2][Bn * Dn];        // ping-pong hx lo-limb
__device__ __half g_Bh[4 * Dn * Dn];       // W_hh hi-limb [2048x512]
__device__ __half g_Bl[4 * Dn * Dn];       // W_hh lo-limb
__device__ float  g_E2[Vn * 4 * Dn];       // embed @ W_ih^T + b_ih + b_hh
__device__ float  g_pwT[Dn * Vn];          // proj_w transposed [K][V]
__device__ int    g_token[Bn];

__device__ __forceinline__ float sigexact(float x) {
    return 1.f / (1.f + expf(-x));
}
__device__ __forceinline__ void splitf(float x, __half& hi, __half& lo) {
    hi = __float2half_rn(x);
    lo = __float2half_rn(x - __half2float(hi));
}

// ---------------- mma / ldmatrix / cp.async wrappers ----------------
__device__ __forceinline__ void mma16816(float* c, const unsigned* a, const unsigned* b) {
    asm volatile(
        "mma.sync.aligned.m16n8k16.row.col.f32.f16.f16.f32 "
        "{%0,%1,%2,%3}, {%4,%5,%6,%7}, {%8,%9}, {%0,%1,%2,%3};"
        : "+f"(c[0]), "+f"(c[1]), "+f"(c[2]), "+f"(c[3])
        : "r"(a[0]), "r"(a[1]), "r"(a[2]), "r"(a[3]), "r"(b[0]), "r"(b[1]));
}
__device__ __forceinline__ void ldm4(unsigned* r, unsigned addr) {
    asm volatile("ldmatrix.sync.aligned.m8n8.x4.shared.b16 {%0,%1,%2,%3}, [%4];"
        : "=r"(r[0]), "=r"(r[1]), "=r"(r[2]), "=r"(r[3]) : "r"(addr));
}
__device__ __forceinline__ void cpasync16(unsigned dst, const void* src) {
    asm volatile("cp.async.ca.shared.global [%0], [%1], 16;" :: "r"(dst), "l"(src));
}
#define CP_COMMIT() asm volatile("cp.async.commit_group;")
#define CP_WAIT2()  asm volatile("cp.async.wait_group 2;")

// ---------------- P1: layernorm(h0) + attention context + init ----------------
__global__ void k_init(const float* __restrict__ fm, const float* __restrict__ pooled,
                       const float* __restrict__ gamma, const float* __restrict__ beta,
                       const float* __restrict__ attnw, const int* __restrict__ sos) {
    extern __shared__ float dyn[];
    float* sfm = dyn;            // 25088 floats
    float* swf = dyn + 25088;    // 512 floats
    __shared__ float red[256];
    __shared__ float saw[64];
    __shared__ float sstat[2];
    __shared__ float sh0[512];

    int b = blockIdx.x;
    int tid = threadIdx.x;

    const float4* fmb = (const float4*)(fm + (size_t)b * 25088);
    for (int i = tid; i < 6272; i += 256) ((float4*)sfm)[i] = fmb[i];
    for (int i = tid; i < 512; i += 256) swf[i] = attnw[i];

    float x0 = pooled[b * Dn + tid];
    float x1 = pooled[b * Dn + 256 + tid];
    red[tid] = x0 + x1;
    __syncthreads();
    for (int s = 128; s > 0; s >>= 1) {
        if (tid < s) red[tid] += red[tid + s];
        __syncthreads();
    }
    if (tid == 0) sstat[0] = red[0] * (1.0f / Dn);
    __syncthreads();
    float mu = sstat[0];
    float d0 = x0 - mu, d1 = x1 - mu;
    red[tid] = d0 * d0 + d1 * d1;
    __syncthreads();
    for (int s = 128; s > 0; s >>= 1) {
        if (tid < s) red[tid] += red[tid + s];
        __syncthreads();
    }
    if (tid == 0) sstat[1] = rsqrtf(red[0] * (1.0f / Dn) + 1e-5f);
    __syncthreads();
    float rs = sstat[1];
    sh0[tid]       = d0 * rs * gamma[tid]       + beta[tid];
    sh0[256 + tid] = d1 * rs * gamma[256 + tid] + beta[256 + tid];

    if (tid < 49) {
        float sc = 0.f;
        #pragma unroll 8
        for (int d = 0; d < 512; d++) sc += sfm[d * 49 + tid] * swf[d];
        saw[tid] = sc;
    }
    __syncthreads();
    if (tid == 0) {
        float mx = -1e30f;
        for (int p = 0; p < 49; p++) mx = fmaxf(mx, saw[p]);
        float sm = 0.f;
        for (int p = 0; p < 49; p++) { float e = expf(saw[p] - mx); saw[p] = e; sm += e; }
        sstat[0] = 1.0f / sm;
    }
    __syncthreads();
    float inv = sstat[0];

    for (int d = tid; d < 512; d += 256) {
        float acc = 0.f;
        #pragma unroll
        for (int p = 0; p < 49; p++) acc += saw[p] * sfm[d * 49 + p];
        float ctx = acc * inv;
        int idx = b * Dn + d;
        g_ctx[idx] = ctx;
        g_c[idx] = 0.f;
        float hx = ctx + sh0[d];
        __half hi, lo;
        splitf(hx, hi, lo);
        g_Ah[0][idx] = hi;
        g_Al[0][idx] = lo;
    }
    if (tid == 0) g_token[b] = *sos;
}

// ---------------- one-time: split W_hh into f16 limbs ----------------
__global__ void k_splitW(const float* __restrict__ W) {
    int idx = blockIdx.x * 256 + threadIdx.x;   // 1048576 total
    float x = W[idx];
    __half hi, lo;
    splitf(x, hi, lo);
    g_Bh[idx] = hi;
    g_Bl[idx] = lo;
}

// ---------------- E2 = embed @ W_ih^T + b_ih + b_hh (one-time) ----------------
__global__ __launch_bounds__(256) void k_e2(const float* __restrict__ emb,
                                            const float* __restrict__ Wih,
                                            const float* __restrict__ bih,
                                            const float* __restrict__ bhh) {
    __shared__ __align__(16) float sA[16 * 68];
    __shared__ __align__(16) float sB[16 * 68];
    int m0 = blockIdx.y * 64;
    int n0 = blockIdx.x * 64;
    int tid = threadIdx.x;
    int tx = tid & 15, ty = tid >> 4;
    int lm = tid >> 2;
    int lk = (tid & 3) * 4;
    const float* Ap = emb + (size_t)(m0 + lm) * Dn + lk;
    const float* Bp = Wih + (size_t)(n0 + lm) * Dn + lk;
    float acc[4][4] = {};
    for (int kt = 0; kt < 512; kt += 16) {
        float4 a = *(const float4*)(Ap + kt);
        float4 bb = *(const float4*)(Bp + kt);
        sA[(lk + 0) * 68 + lm] = a.x;  sA[(lk + 1) * 68 + lm] = a.y;
        sA[(lk + 2) * 68 + lm] = a.z;  sA[(lk + 3) * 68 + lm] = a.w;
        sB[(lk + 0) * 68 + lm] = bb.x; sB[(lk + 1) * 68 + lm] = bb.y;
        sB[(lk + 2) * 68 + lm] = bb.z; sB[(lk + 3) * 68 + lm] = bb.w;
        __syncthreads();
        #pragma unroll
        for (int k = 0; k < 16; k++) {
            float4 av = *(const float4*)&sA[k * 68 + ty * 4];
            float4 bv = *(const float4*)&sB[k * 68 + tx * 4];
            float ar[4] = {av.x, av.y, av.z, av.w};
            float br[4] = {bv.x, bv.y, bv.z, bv.w};
            #pragma unroll
            for (int i = 0; i < 4; i++)
                #pragma unroll
                for (int j = 0; j < 4; j++) acc[i][j] += ar[i] * br[j];
        }
        __syncthreads();
    }
    int gj0 = n0 + tx * 4;
    float4 b1 = *(const float4*)&bih[gj0];
    float4 b2 = *(const float4*)&bhh[gj0];
    #pragma unroll
    for (int i = 0; i < 4; i++) {
        int gv = m0 + ty * 4 + i;
        float4 o;
        o.x = acc[i][0] + b1.x + b2.x;
        o.y = acc[i][1] + b1.y + b2.y;
        o.z = acc[i][2] + b1.z + b2.z;
        o.w = acc[i][3] + b1.w + b2.w;
        *(float4*)&g_E2[(size_t)gv * 2048 + gj0] = o;
    }
}

// ---------------- proj_w transpose (one-time) ----------------
__global__ void k_tw(const float* __restrict__ projw) {
    int idx = blockIdx.x * 256 + threadIdx.x;   // 65536 total
    int vv = idx >> 9;
    int kk = idx & 511;
    g_pwT[kk * 128 + vv] = projw[idx];
}

// ---------------- per-step: gates GEMM (tensor cores, f16 2-limb) + LSTM cell ----
// C = Ah*Bh + Ah*Bl + Al*Bh (fp32 accum). Block: 128(batch) x 128(n).
// N gate-interleaved: nl -> gate=(nl>>3)&3, dloc=(nl>>5)*8+(nl&7) -> register LSTM.
// KEY CHANGE vs R6: the 48 MMAs per k-iter are issued as THREE PASSES over all 16
// (mi,ni) tiles (HH pass, HL pass, LH pass) instead of 3 back-to-back MMAs per tile.
// Accumulator reuse distance 1 -> 16 instructions; covers HMMA latency.
// Numerically identical (per-element order still HH,HL,LH per k-step).
#define ST_ROW 48
#define OFF_AH 0
#define OFF_AL 6144
#define OFF_BH 12288
#define OFF_BL 18432
#define STAGE_BYTES 24576
#define SMEM_GATES (STAGE_BYTES * 4)

__global__ __launch_bounds__(256, 1) void k_gates(int par) {
    extern __shared__ char sdyn[];
    const __half* Ahp = g_Ah[par];
    const __half* Alp = g_Al[par];
    __half* AhO = g_Ah[par ^ 1];
    __half* AlO = g_Al[par ^ 1];

    int tid = threadIdx.x;
    int lane = tid & 31;
    int wid = tid >> 5;
    int d0 = blockIdx.x * 32;
    int bm0 = blockIdx.y * 128;
    int m0w = (wid >> 2) * 64;
    int wn = wid & 3;               // 8-wide d-subrange within block's 32 d's

    unsigned sb = (unsigned)__cvta_generic_to_shared(sdyn);

    // ldmatrix lane base addresses (stage 0)
    unsigned aAH[4], aAL[4], bAH[2], bAL[2];
    #pragma unroll
    for (int mi = 0; mi < 4; mi++) {
        int row = m0w + mi * 16 + ((lane >> 3) & 1) * 8 + (lane & 7);
        unsigned off = (unsigned)(row * ST_ROW + ((lane >> 4) & 1) * 16);
        aAH[mi] = sb + OFF_AH + off;
        aAL[mi] = sb + OFF_AL + off;
    }
    #pragma unroll
    for (int pi = 0; pi < 2; pi++) {
        int row = wn * 32 + pi * 16 + ((lane >> 4) & 1) * 8 + (lane & 7);
        unsigned off = (unsigned)(row * ST_ROW + ((lane >> 3) & 1) * 16);
        bAH[pi] = sb + OFF_BH + off;
        bAL[pi] = sb + OFF_BL + off;
    }

    // staging: each thread copies 16B per array per stage
    int srow = tid >> 1, shalf = tid & 1;
    const char* gAh = (const char*)(Ahp + (size_t)(bm0 + srow) * Dn + shalf * 8);
    const char* gAl = (const char*)(Alp + (size_t)(bm0 + srow) * Dn + shalf * 8);
    int grow = ((srow >> 3) & 3) * 512 + d0 + (srow >> 5) * 8 + (srow & 7);
    const char* gBh = (const char*)(g_Bh + (size_t)grow * Dn + shalf * 8);
    const char* gBl = (const char*)(g_Bl + (size_t)grow * Dn + shalf * 8);
    unsigned stOff = (unsigned)(srow * ST_ROW + shalf * 16);

    float c[4][4][4];
    #pragma unroll
    for (int mi = 0; mi < 4; mi++)
        #pragma unroll
        for (int ni = 0; ni < 4; ni++)
            #pragma unroll
            for (int q = 0; q < 4; q++) c[mi][ni][q] = 0.f;

    // prefetch stages 0..2
    #pragma unroll
    for (int s = 0; s < 3; s++) {
        unsigned so = sb + (unsigned)(s * STAGE_BYTES);
        int go = s * 32;
        cpasync16(so + OFF_AH + stOff, gAh + go);
        cpasync16(so + OFF_AL + stOff, gAl + go);
        cpasync16(so + OFF_BH + stOff, gBh + go);
        cpasync16(so + OFF_BL + stOff, gBl + go);
        CP_COMMIT();
    }

    for (int kt = 0; kt < 32; kt++) {
        CP_WAIT2();
        __syncthreads();
        unsigned so = (unsigned)((kt & 3) * STAGE_BYTES);

        unsigned AH[4][4], AL[4][4], BH[2][4], BL[2][4];
        #pragma unroll
        for (int mi = 0; mi < 4; mi++) { ldm4(AH[mi], aAH[mi] + so); ldm4(AL[mi], aAL[mi] + so); }
        #pragma unroll
        for (int pi = 0; pi < 2; pi++) { ldm4(BH[pi], bAH[pi] + so); ldm4(BL[pi], bAL[pi] + so); }

        // issue stage kt+3 while tensor cores crunch this one
        if (kt + 3 < 32) {
            unsigned sw = sb + (unsigned)(((kt + 3) & 3) * STAGE_BYTES);
            int go = (kt + 3) * 32;
            cpasync16(sw + OFF_AH + stOff, gAh + go);
            cpasync16(sw + OFF_AL + stOff, gAl + go);
            cpasync16(sw + OFF_BH + stOff, gBh + go);
            cpasync16(sw + OFF_BL + stOff, gBl + go);
        }
        CP_COMMIT();

        // pass 1: AH * BH  (16 independent MMAs)
        #pragma unroll
        for (int mi = 0; mi < 4; mi++)
            #pragma unroll
            for (int ni = 0; ni < 4; ni++)
                mma16816(c[mi][ni], AH[mi], &BH[ni >> 1][(ni & 1) * 2]);
        // pass 2: AH * BL
        #pragma unroll
        for (int mi = 0; mi < 4; mi++)
            #pragma unroll
            for (int ni = 0; ni < 4; ni++)
                mma16816(c[mi][ni], AH[mi], &BL[ni >> 1][(ni & 1) * 2]);
        // pass 3: AL * BH
        #pragma unroll
        for (int mi = 0; mi < 4; mi++)
            #pragma unroll
            for (int ni = 0; ni < 4; ni++)
                mma16816(c[mi][ni], AL[mi], &BH[ni >> 1][(ni & 1) * 2]);
    }

    // register LSTM epilogue: c[mi][gate][frag] holds all 4 gates of each element
    int g = lane >> 2, tg = lane & 3;
    int ddb = wn * 8 + tg * 2;
    #pragma unroll
    for (int mi = 0; mi < 4; mi++) {
        #pragma unroll
        for (int q = 0; q < 2; q++) {
            int row = bm0 + m0w + mi * 16 + g + q * 8;
            int tok = g_token[row];
            const float* E = g_E2 + (size_t)tok * 2048 + d0 + ddb;
            float2 ei = *(const float2*)(E);
            float2 ef = *(const float2*)(E + 512);
            float2 eg = *(const float2*)(E + 1024);
            float2 eo = *(const float2*)(E + 1536);
            int idx = row * Dn + d0 + ddb;
            float2 cold = *(const float2*)&g_c[idx];
            float2 ctx = *(const float2*)&g_ctx[idx];

            float gi = c[mi][0][q * 2 + 0] + ei.x;
            float gf = c[mi][1][q * 2 + 0] + ef.x;
            float gg = c[mi][2][q * 2 + 0] + eg.x;
            float go = c[mi][3][q * 2 + 0] + eo.x;
            float cn0 = sigexact(gf) * cold.x + sigexact(gi) * tanhf(gg);
            float hn0 = sigexact(go) * tanhf(cn0);

            gi = c[mi][0][q * 2 + 1] + ei.y;
            gf = c[mi][1][q * 2 + 1] + ef.y;
            gg = c[mi][2][q * 2 + 1] + eg.y;
            go = c[mi][3][q * 2 + 1] + eo.y;
            float cn1 = sigexact(gf) * cold.y + sigexact(gi) * tanhf(gg);
            float hn1 = sigexact(go) * tanhf(cn1);

            *(float2*)&g_c[idx] = make_float2(cn0, cn1);
            *(float2*)&g_h[idx] = make_float2(hn0, hn1);
            float hx0 = hn0 + ctx.x;
            float hx1 = hn1 + ctx.y;
            __half h0h, h0l, h1h, h1l;
            splitf(hx0, h0h, h0l);
            splitf(hx1, h1h, h1l);
            *(__half2*)&AhO[idx] = __halves2half2(h0h, h1h);
            *(__half2*)&AlO[idx] = __halves2half2(h0l, h1l);
        }
    }
}

// ---------------- per-step: logits GEMM + argmax + strided output ----------------
__global__ __launch_bounds__(256) void k_logits(int t, const float* __restrict__ projb,
                                                float* __restrict__ out) {
    __shared__ __align__(16) float sHT[512 * 12];   // [k][row], stride 12
    __shared__ float sL[8 * 128];

    int b0 = blockIdx.x * 8;
    int tid = threadIdx.x;
    int lane = tid & 31;
    int wid = tid >> 5;

    {
        int row = wid;
        #pragma unroll
        for (int it = 0; it < 4; it++) {
            int k4 = lane + 32 * it;
            float4 hv = *(const float4*)&g_h[(size_t)(b0 + row) * Dn + k4 * 4];
            sHT[(k4 * 4 + 0) * 12 + row] = hv.x;
            sHT[(k4 * 4 + 1) * 12 + row] = hv.y;
            sHT[(k4 * 4 + 2) * 12 + row] = hv.z;
            sHT[(k4 * 4 + 3) * 12 + row] = hv.w;
        }
    }
    __syncthreads();

    int rbase = (wid >> 2) * 4;
    int v = (wid & 3) * 32 + lane;
    const float* P = g_pwT + v;

    float a0 = 0.f, a1 = 0.f, a2 = 0.f, a3 = 0.f;
    #pragma unroll 4
    for (int k = 0; k < 512; k += 4) {
        float p0 = __ldg(&P[(k + 0) * 128]);
        float p1 = __ldg(&P[(k + 1) * 128]);
        float p2 = __ldg(&P[(k + 2) * 128]);
        float p3 = __ldg(&P[(k + 3) * 128]);
        float4 hA = *(const float4*)&sHT[(k + 0) * 12 + rbase];
        float4 hB = *(const float4*)&sHT[(k + 1) * 12 + rbase];
        float4 hC = *(const float4*)&sHT[(k + 2) * 12 + rbase];
        float4 hD = *(const float4*)&sHT[(k + 3) * 12 + rbase];
        a0 += hA.x * p0 + hB.x * p1 + hC.x * p2 + hD.x * p3;
        a1 += hA.y * p0 + hB.y * p1 + hC.y * p2 + hD.y * p3;
        a2 += hA.z * p0 + hB.z * p1 + hC.z * p2 + hD.z * p3;
        a3 += hA.w * p0 + hB.w * p1 + hC.w * p2 + hD.w * p3;
    }

    float pb = projb[v];
    float lg[4] = {a0 + pb, a1 + pb, a2 + pb, a3 + pb};
    #pragma unroll
    for (int r = 0; r < 4; r++) {
        sL[(rbase + r) * 128 + v] = lg[r];
        out[(size_t)(b0 + rbase + r) * (Vn * Tn) + (size_t)v * Tn + t] = lg[r];
    }
    __syncthreads();

    int w = wid;
    float best = sL[w * 128 + lane];
    int bidx = lane;
    #pragma unroll
    for (int off = 32; off < 128; off += 32) {
        float vv = sL[w * 128 + lane + off];
        if (vv > best) { best = vv; bidx = lane + off; }
    }
    #pragma unroll
    for (int s = 16; s > 0; s >>= 1) {
        float ov = __shfl_down_sync(0xffffffffu, best, s);
        int oi = __shfl_down_sync(0xffffffffu, bidx, s);
        if (ov > best || (ov == best && oi < bidx)) { best = ov; bidx = oi; }
    }
    if (lane == 0) g_token[b0 + w] = bidx;
}

// ---------------- launch ----------------
extern "C" void kernel_launch(void* const* d_in, const int* in_sizes, int n_in,
                              void* d_out, int out_size) {
    const float* fm     = (const float*)d_in[0];
    const float* pooled = (const float*)d_in[1];
    const float* gamma  = (const float*)d_in[2];
    const float* beta   = (const float*)d_in[3];
    const float* Wih    = (const float*)d_in[4];
    const float* Whh    = (const float*)d_in[5];
    const float* bih    = (const float*)d_in[6];
    const float* bhh    = (const float*)d_in[7];
    const float* emb    = (const float*)d_in[8];
    const float* attnw  = (const float*)d_in[9];
    // d_in[10] = attn_b: cancels in softmax (constant over the axis)
    const float* projw  = (const float*)d_in[11];
    const float* projb  = (const float*)d_in[12];
    const int*   sos    = (const int*)d_in[13];
    float* out = (float*)d_out;

    const int dynBytes = (25088 + 512) * 4;
    cudaFuncSetAttribute(k_init, cudaFuncAttributeMaxDynamicSharedMemorySize, dynBytes);
    cudaFuncSetAttribute(k_gates, cudaFuncAttributeMaxDynamicSharedMemorySize, SMEM_GATES);

    k_init<<<Bn, 256, dynBytes>>>(fm, pooled, gamma, beta, attnw, sos);
    k_splitW<<<4096, 256>>>(Whh);
    k_e2<<<dim3(32, 2), 256>>>(emb, Wih, bih, bhh);
    k_tw<<<256, 256>>>(projw);

    for (int t = 0; t < Tn; t++) {
        k_gates<<<dim3(16, 8), 256, SMEM_GATES>>>(t & 1);
        k_logits<<<128, 256>>>(t, projb, out);
    }
}

// round 9
// speedup vs baseline: 2.9243x; 1.0146x over previous
#include <cuda_runtime.h>
#include <cuda_fp16.h>
#include <math.h>

#define Bn 1024
#define Dn 512
#define Vn 128
#define Tn 201

// ---------------- device scratch ----------------
__device__ float  g_h[Bn * Dn];            // h_t
__device__ float  g_c[Bn * Dn];
__device__ float  g_ctx[Bn * Dn];
__device__ __half g_Ah[2][Bn * Dn];        // ping-pong hx hi-limb
__device__ __half g_Al[2][Bn * Dn];        // ping-pong hx lo-limb
__device__ __half g_Bh[4 * Dn * Dn];       // W_hh hi-limb [2048x512]
__device__ __half g_Bl[4 * Dn * Dn];       // W_hh lo-limb
__device__ float  g_E2[Vn * 4 * Dn];       // embed @ W_ih^T + b_ih + b_hh
__device__ float  g_pwT[Dn * Vn];          // proj_w transposed [K][V]
__device__ int    g_token[Bn];
__device__ int    g_done;                  // cumulative finished logits blocks

__device__ __forceinline__ float sigexact(float x) {
    return 1.f / (1.f + expf(-x));
}
__device__ __forceinline__ void splitf(float x, __half& hi, __half& lo) {
    hi = __float2half_rn(x);
    lo = __float2half_rn(x - __half2float(hi));
}

// ---------------- mma / ldmatrix / cp.async wrappers ----------------
__device__ __forceinline__ void mma16816(float* c, const unsigned* a, const unsigned* b) {
    asm volatile(
        "mma.sync.aligned.m16n8k16.row.col.f32.f16.f16.f32 "
        "{%0,%1,%2,%3}, {%4,%5,%6,%7}, {%8,%9}, {%0,%1,%2,%3};"
        : "+f"(c[0]), "+f"(c[1]), "+f"(c[2]), "+f"(c[3])
        : "r"(a[0]), "r"(a[1]), "r"(a[2]), "r"(a[3]), "r"(b[0]), "r"(b[1]));
}
__device__ __forceinline__ void ldm4(unsigned* r, unsigned addr) {
    asm volatile("ldmatrix.sync.aligned.m8n8.x4.shared.b16 {%0,%1,%2,%3}, [%4];"
        : "=r"(r[0]), "=r"(r[1]), "=r"(r[2]), "=r"(r[3]) : "r"(addr));
}
__device__ __forceinline__ void cpasync16(unsigned dst, const void* src) {
    asm volatile("cp.async.ca.shared.global [%0], [%1], 16;" :: "r"(dst), "l"(src));
}
#define CP_COMMIT() asm volatile("cp.async.commit_group;")
#define CP_WAIT2()  asm volatile("cp.async.wait_group 2;")

// ---------------- P1: layernorm(h0) + attention context + init ----------------
__global__ void k_init(const float* __restrict__ fm, const float* __restrict__ pooled,
                       const float* __restrict__ gamma, const float* __restrict__ beta,
                       const float* __restrict__ attnw, const int* __restrict__ sos) {
    extern __shared__ float dyn[];
    float* sfm = dyn;            // 25088 floats
    float* swf = dyn + 25088;    // 512 floats
    __shared__ float red[256];
    __shared__ float saw[64];
    __shared__ float sstat[2];
    __shared__ float sh0[512];

    int b = blockIdx.x;
    int tid = threadIdx.x;

    const float4* fmb = (const float4*)(fm + (size_t)b * 25088);
    for (int i = tid; i < 6272; i += 256) ((float4*)sfm)[i] = fmb[i];
    for (int i = tid; i < 512; i += 256) swf[i] = attnw[i];

    float x0 = pooled[b * Dn + tid];
    float x1 = pooled[b * Dn + 256 + tid];
    red[tid] = x0 + x1;
    __syncthreads();
    for (int s = 128; s > 0; s >>= 1) {
        if (tid < s) red[tid] += red[tid + s];
        __syncthreads();
    }
    if (tid == 0) sstat[0] = red[0] * (1.0f / Dn);
    __syncthreads();
    float mu = sstat[0];
    float d0 = x0 - mu, d1 = x1 - mu;
    red[tid] = d0 * d0 + d1 * d1;
    __syncthreads();
    for (int s = 128; s > 0; s >>= 1) {
        if (tid < s) red[tid] += red[tid + s];
        __syncthreads();
    }
    if (tid == 0) sstat[1] = rsqrtf(red[0] * (1.0f / Dn) + 1e-5f);
    __syncthreads();
    float rs = sstat[1];
    sh0[tid]       = d0 * rs * gamma[tid]       + beta[tid];
    sh0[256 + tid] = d1 * rs * gamma[256 + tid] + beta[256 + tid];

    if (tid < 49) {
        float sc = 0.f;
        #pragma unroll 8
        for (int d = 0; d < 512; d++) sc += sfm[d * 49 + tid] * swf[d];
        saw[tid] = sc;
    }
    __syncthreads();
    if (tid == 0) {
        float mx = -1e30f;
        for (int p = 0; p < 49; p++) mx = fmaxf(mx, saw[p]);
        float sm = 0.f;
        for (int p = 0; p < 49; p++) { float e = expf(saw[p] - mx); saw[p] = e; sm += e; }
        sstat[0] = 1.0f / sm;
    }
    __syncthreads();
    float inv = sstat[0];

    for (int d = tid; d < 512; d += 256) {
        float acc = 0.f;
        #pragma unroll
        for (int p = 0; p < 49; p++) acc += saw[p] * sfm[d * 49 + p];
        float ctx = acc * inv;
        int idx = b * Dn + d;
        g_ctx[idx] = ctx;
        g_c[idx] = 0.f;
        float hx = ctx + sh0[d];
        __half hi, lo;
        splitf(hx, hi, lo);
        g_Ah[0][idx] = hi;
        g_Al[0][idx] = lo;
    }
    if (tid == 0) {
        g_token[b] = *sos;
        if (b == 0) g_done = 0;
    }
}

// ---------------- one-time: split W_hh into f16 limbs ----------------
__global__ void k_splitW(const float* __restrict__ W) {
    int idx = blockIdx.x * 256 + threadIdx.x;   // 1048576 total
    float x = W[idx];
    __half hi, lo;
    splitf(x, hi, lo);
    g_Bh[idx] = hi;
    g_Bl[idx] = lo;
}

// ---------------- E2 = embed @ W_ih^T + b_ih + b_hh (one-time) ----------------
__global__ __launch_bounds__(256) void k_e2(const float* __restrict__ emb,
                                            const float* __restrict__ Wih,
                                            const float* __restrict__ bih,
                                            const float* __restrict__ bhh) {
    __shared__ __align__(16) float sA[16 * 68];
    __shared__ __align__(16) float sB[16 * 68];
    int m0 = blockIdx.y * 64;
    int n0 = blockIdx.x * 64;
    int tid = threadIdx.x;
    int tx = tid & 15, ty = tid >> 4;
    int lm = tid >> 2;
    int lk = (tid & 3) * 4;
    const float* Ap = emb + (size_t)(m0 + lm) * Dn + lk;
    const float* Bp = Wih + (size_t)(n0 + lm) * Dn + lk;
    float acc[4][4] = {};
    for (int kt = 0; kt < 512; kt += 16) {
        float4 a = *(const float4*)(Ap + kt);
        float4 bb = *(const float4*)(Bp + kt);
        sA[(lk + 0) * 68 + lm] = a.x;  sA[(lk + 1) * 68 + lm] = a.y;
        sA[(lk + 2) * 68 + lm] = a.z;  sA[(lk + 3) * 68 + lm] = a.w;
        sB[(lk + 0) * 68 + lm] = bb.x; sB[(lk + 1) * 68 + lm] = bb.y;
        sB[(lk + 2) * 68 + lm] = bb.z; sB[(lk + 3) * 68 + lm] = bb.w;
        __syncthreads();
        #pragma unroll
        for (int k = 0; k < 16; k++) {
            float4 av = *(const float4*)&sA[k * 68 + ty * 4];
            float4 bv = *(const float4*)&sB[k * 68 + tx * 4];
            float ar[4] = {av.x, av.y, av.z, av.w};
            float br[4] = {bv.x, bv.y, bv.z, bv.w};
            #pragma unroll
            for (int i = 0; i < 4; i++)
                #pragma unroll
                for (int j = 0; j < 4; j++) acc[i][j] += ar[i] * br[j];
        }
        __syncthreads();
    }
    int gj0 = n0 + tx * 4;
    float4 b1 = *(const float4*)&bih[gj0];
    float4 b2 = *(const float4*)&bhh[gj0];
    #pragma unroll
    for (int i = 0; i < 4; i++) {
        int gv = m0 + ty * 4 + i;
        float4 o;
        o.x = acc[i][0] + b1.x + b2.x;
        o.y = acc[i][1] + b1.y + b2.y;
        o.z = acc[i][2] + b1.z + b2.z;
        o.w = acc[i][3] + b1.w + b2.w;
        *(float4*)&g_E2[(size_t)gv * 2048 + gj0] = o;
    }
}

// ---------------- proj_w transpose (one-time) ----------------
__global__ void k_tw(const float* __restrict__ projw) {
    int idx = blockIdx.x * 256 + threadIdx.x;   // 65536 total
    int vv = idx >> 9;
    int kk = idx & 511;
    g_pwT[kk * 128 + vv] = projw[idx];
}

// ---------------- fused per-step kernel ----------------
// bids 0..127   : gates(t)     (placed first -> 1 per SM; tensor pipe)
// bids 128..255 : logits(t-1)  (co-resident; fma/lsu pipes; skipped at t=0)
// gates epilogue waits for ALL logits blocks of this launch via g_done
// (release: threadfence+atomicAdd in logits; acquire: spin+fence in gates).
// __launch_bounds__(256,2) guarantees 2-block co-residency -> no deadlock.
#define ST_ROW 48
#define OFF_AH 0
#define OFF_AL 6144
#define OFF_BH 12288
#define OFF_BL 18432
#define STAGE_BYTES 24576
#define SMEM_STEP (STAGE_BYTES * 4)   // 96KB; logits path uses a 29KB carve

__global__ __launch_bounds__(256, 2) void k_step(int t, const float* __restrict__ projb,
                                                 float* __restrict__ out) {
    extern __shared__ char sdyn[];
    int bid = blockIdx.x;
    int tid = threadIdx.x;
    int lane = tid & 31;
    int wid = tid >> 5;

    if (bid < 128) {
        // ================= GATES(t) =================
        int par = t & 1;
        const __half* Ahp = g_Ah[par];
        const __half* Alp = g_Al[par];
        __half* AhO = g_Ah[par ^ 1];
        __half* AlO = g_Al[par ^ 1];

        int d0 = (bid & 15) * 32;
        int bm0 = (bid >> 4) * 128;
        int m0w = (wid >> 2) * 64;
        int wn = wid & 3;

        unsigned sb = (unsigned)__cvta_generic_to_shared(sdyn);

        unsigned aAH[4], aAL[4], bAH[2], bAL[2];
        #pragma unroll
        for (int mi = 0; mi < 4; mi++) {
            int row = m0w + mi * 16 + ((lane >> 3) & 1) * 8 + (lane & 7);
            unsigned off = (unsigned)(row * ST_ROW + ((lane >> 4) & 1) * 16);
            aAH[mi] = sb + OFF_AH + off;
            aAL[mi] = sb + OFF_AL + off;
        }
        #pragma unroll
        for (int pi = 0; pi < 2; pi++) {
            int row = wn * 32 + pi * 16 + ((lane >> 4) & 1) * 8 + (lane & 7);
            unsigned off = (unsigned)(row * ST_ROW + ((lane >> 3) & 1) * 16);
            bAH[pi] = sb + OFF_BH + off;
            bAL[pi] = sb + OFF_BL + off;
        }

        int srow = tid >> 1, shalf = tid & 1;
        const char* gAh = (const char*)(Ahp + (size_t)(bm0 + srow) * Dn + shalf * 8);
        const char* gAl = (const char*)(Alp + (size_t)(bm0 + srow) * Dn + shalf * 8);
        int grow = ((srow >> 3) & 3) * 512 + d0 + (srow >> 5) * 8 + (srow & 7);
        const char* gBh = (const char*)(g_Bh + (size_t)grow * Dn + shalf * 8);
        const char* gBl = (const char*)(g_Bl + (size_t)grow * Dn + shalf * 8);
        unsigned stOff = (unsigned)(srow * ST_ROW + shalf * 16);

        float c[4][4][4];
        #pragma unroll
        for (int mi = 0; mi < 4; mi++)
            #pragma unroll
            for (int ni = 0; ni < 4; ni++)
                #pragma unroll
                for (int q = 0; q < 4; q++) c[mi][ni][q] = 0.f;

        #pragma unroll
        for (int s = 0; s < 3; s++) {
            unsigned so = sb + (unsigned)(s * STAGE_BYTES);
            int go = s * 32;
            cpasync16(so + OFF_AH + stOff, gAh + go);
            cpasync16(so + OFF_AL + stOff, gAl + go);
            cpasync16(so + OFF_BH + stOff, gBh + go);
            cpasync16(so + OFF_BL + stOff, gBl + go);
            CP_COMMIT();
        }

        for (int kt = 0; kt < 32; kt++) {
            CP_WAIT2();
            __syncthreads();
            unsigned so = (unsigned)((kt & 3) * STAGE_BYTES);

            unsigned AH[4][4], AL[4][4], BH[2][4], BL[2][4];
            #pragma unroll
            for (int mi = 0; mi < 4; mi++) { ldm4(AH[mi], aAH[mi] + so); ldm4(AL[mi], aAL[mi] + so); }
            #pragma unroll
            for (int pi = 0; pi < 2; pi++) { ldm4(BH[pi], bAH[pi] + so); ldm4(BL[pi], bAL[pi] + so); }

            if (kt + 3 < 32) {
                unsigned sw = sb + (unsigned)(((kt + 3) & 3) * STAGE_BYTES);
                int go = (kt + 3) * 32;
                cpasync16(sw + OFF_AH + stOff, gAh + go);
                cpasync16(sw + OFF_AL + stOff, gAl + go);
                cpasync16(sw + OFF_BH + stOff, gBh + go);
                cpasync16(sw + OFF_BL + stOff, gBl + go);
            }
            CP_COMMIT();

            #pragma unroll
            for (int mi = 0; mi < 4; mi++)
                #pragma unroll
                for (int ni = 0; ni < 4; ni++)
                    mma16816(c[mi][ni], AH[mi], &BH[ni >> 1][(ni & 1) * 2]);
            #pragma unroll
            for (int mi = 0; mi < 4; mi++)
                #pragma unroll
                for (int ni = 0; ni < 4; ni++)
                    mma16816(c[mi][ni], AH[mi], &BL[ni >> 1][(ni & 1) * 2]);
            #pragma unroll
            for (int mi = 0; mi < 4; mi++)
                #pragma unroll
                for (int ni = 0; ni < 4; ni++)
                    mma16816(c[mi][ni], AL[mi], &BH[ni >> 1][(ni & 1) * 2]);
        }

        // wait for this launch's logits blocks (token(t-1) producers)
        if (tid == 0) {
            int target = 128 * t;
            while (atomicAdd(&g_done, 0) < target) {}
            __threadfence();
        }
        __syncthreads();

        // register LSTM epilogue
        int g = lane >> 2, tg = lane & 3;
        int ddb = wn * 8 + tg * 2;
        #pragma unroll
        for (int mi = 0; mi < 4; mi++) {
            #pragma unroll
            for (int q = 0; q < 2; q++) {
                int row = bm0 + m0w + mi * 16 + g + q * 8;
                int tok = g_token[row];
                const float* E = g_E2 + (size_t)tok * 2048 + d0 + ddb;
                float2 ei = *(const float2*)(E);
                float2 ef = *(const float2*)(E + 512);
                float2 eg = *(const float2*)(E + 1024);
                float2 eo = *(const float2*)(E + 1536);
                int idx = row * Dn + d0 + ddb;
                float2 cold = *(const float2*)&g_c[idx];
                float2 ctx = *(const float2*)&g_ctx[idx];

                float gi = c[mi][0][q * 2 + 0] + ei.x;
                float gf = c[mi][1][q * 2 + 0] + ef.x;
                float gg = c[mi][2][q * 2 + 0] + eg.x;
                float go = c[mi][3][q * 2 + 0] + eo.x;
                float cn0 = sigexact(gf) * cold.x + sigexact(gi) * tanhf(gg);
                float hn0 = sigexact(go) * tanhf(cn0);

                gi = c[mi][0][q * 2 + 1] + ei.y;
                gf = c[mi][1][q * 2 + 1] + ef.y;
                gg = c[mi][2][q * 2 + 1] + eg.y;
                go = c[mi][3][q * 2 + 1] + eo.y;
                float cn1 = sigexact(gf) * cold.y + sigexact(gi) * tanhf(gg);
                float hn1 = sigexact(go) * tanhf(cn1);

                *(float2*)&g_c[idx] = make_float2(cn0, cn1);
                *(float2*)&g_h[idx] = make_float2(hn0, hn1);
                float hx0 = hn0 + ctx.x;
                float hx1 = hn1 + ctx.y;
                __half h0h, h0l, h1h, h1l;
                splitf(hx0, h0h, h0l);
                splitf(hx1, h1h, h1l);
                *(__half2*)&AhO[idx] = __halves2half2(h0h, h1h);
                *(__half2*)&AlO[idx] = __halves2half2(h0l, h1l);
            }
        }
    } else {
        // ================= LOGITS(t-1) =================
        if (t == 0) return;
        int ts = t - 1;
        float* sHT = (float*)sdyn;                    // 512*12 floats
        float* sL = (float*)(sdyn + 512 * 12 * 4);    // 8*128 floats

        int b0 = (bid - 128) * 8;

        {
            int row = wid;
            #pragma unroll
            for (int it = 0; it < 4; it++) {
                int k4 = lane + 32 * it;
                float4 hv = *(const float4*)&g_h[(size_t)(b0 + row) * Dn + k4 * 4];
                sHT[(k4 * 4 + 0) * 12 + row] = hv.x;
                sHT[(k4 * 4 + 1) * 12 + row] = hv.y;
                sHT[(k4 * 4 + 2) * 12 + row] = hv.z;
                sHT[(k4 * 4 + 3) * 12 + row] = hv.w;
            }
        }
        __syncthreads();

        int rbase = (wid >> 2) * 4;
        int v = (wid & 3) * 32 + lane;
        const float* P = g_pwT + v;

        float a0 = 0.f, a1 = 0.f, a2 = 0.f, a3 = 0.f;
        #pragma unroll 4
        for (int k = 0; k < 512; k += 4) {
            float p0 = __ldg(&P[(k + 0) * 128]);
            float p1 = __ldg(&P[(k + 1) * 128]);
            float p2 = __ldg(&P[(k + 2) * 128]);
            float p3 = __ldg(&P[(k + 3) * 128]);
            float4 hA = *(const float4*)&sHT[(k + 0) * 12 + rbase];
            float4 hB = *(const float4*)&sHT[(k + 1) * 12 + rbase];
            float4 hC = *(const float4*)&sHT[(k + 2) * 12 + rbase];
            float4 hD = *(const float4*)&sHT[(k + 3) * 12 + rbase];
            a0 += hA.x * p0 + hB.x * p1 + hC.x * p2 + hD.x * p3;
            a1 += hA.y * p0 + hB.y * p1 + hC.y * p2 + hD.y * p3;
            a2 += hA.z * p0 + hB.z * p1 + hC.z * p2 + hD.z * p3;
            a3 += hA.w * p0 + hB.w * p1 + hC.w * p2 + hD.w * p3;
        }

        float pb = projb[v];
        float lg[4] = {a0 + pb, a1 + pb, a2 + pb, a3 + pb};
        #pragma unroll
        for (int r = 0; r < 4; r++) {
            sL[(rbase + r) * 128 + v] = lg[r];
            out[(size_t)(b0 + rbase + r) * (Vn * Tn) + (size_t)v * Tn + ts] = lg[r];
        }
        __syncthreads();

        int w = wid;
        float best = sL[w * 128 + lane];
        int bidx = lane;
        #pragma unroll
        for (int off = 32; off < 128; off += 32) {
            float vv = sL[w * 128 + lane + off];
            if (vv > best) { best = vv; bidx = lane + off; }
        }
        #pragma unroll
        for (int s = 16; s > 0; s >>= 1) {
            float ov = __shfl_down_sync(0xffffffffu, best, s);
            int oi = __shfl_down_sync(0xffffffffu, bidx, s);
            if (ov > best || (ov == best && oi < bidx)) { best = ov; bidx = oi; }
        }
        if (lane == 0) g_token[b0 + w] = bidx;
        __syncthreads();
        __threadfence();
        if (tid == 0) atomicAdd(&g_done, 1);   // release: all writes visible first
    }
}

// ---------------- standalone final logits (step Tn-1) ----------------
__global__ __launch_bounds__(256) void k_logits(int t, const float* __restrict__ projb,
                                                float* __restrict__ out) {
    __shared__ __align__(16) float sHT[512 * 12];
    __shared__ float sL[8 * 128];

    int b0 = blockIdx.x * 8;
    int tid = threadIdx.x;
    int lane = tid & 31;
    int wid = tid >> 5;

    {
        int row = wid;
        #pragma unroll
        for (int it = 0; it < 4; it++) {
            int k4 = lane + 32 * it;
            float4 hv = *(const float4*)&g_h[(size_t)(b0 + row) * Dn + k4 * 4];
            sHT[(k4 * 4 + 0) * 12 + row] = hv.x;
            sHT[(k4 * 4 + 1) * 12 + row] = hv.y;
            sHT[(k4 * 4 + 2) * 12 + row] = hv.z;
            sHT[(k4 * 4 + 3) * 12 + row] = hv.w;
        }
    }
    __syncthreads();

    int rbase = (wid >> 2) * 4;
    int v = (wid & 3) * 32 + lane;
    const float* P = g_pwT + v;

    float a0 = 0.f, a1 = 0.f, a2 = 0.f, a3 = 0.f;
    #pragma unroll 4
    for (int k = 0; k < 512; k += 4) {
        float p0 = __ldg(&P[(k + 0) * 128]);
        float p1 = __ldg(&P[(k + 1) * 128]);
        float p2 = __ldg(&P[(k + 2) * 128]);
        float p3 = __ldg(&P[(k + 3) * 128]);
        float4 hA = *(const float4*)&sHT[(k + 0) * 12 + rbase];
        float4 hB = *(const float4*)&sHT[(k + 1) * 12 + rbase];
        float4 hC = *(const float4*)&sHT[(k + 2) * 12 + rbase];
        float4 hD = *(const float4*)&sHT[(k + 3) * 12 + rbase];
        a0 += hA.x * p0 + hB.x * p1 + hC.x * p2 + hD.x * p3;
        a1 += hA.y * p0 + hB.y * p1 + hC.y * p2 + hD.y * p3;
        a2 += hA.z * p0 + hB.z * p1 + hC.z * p2 + hD.z * p3;
        a3 += hA.w * p0 + hB.w * p1 + hC.w * p2 + hD.w * p3;
    }

    float pb = projb[v];
    #pragma unroll
    for (int r = 0; r < 4; r++)
        out[(size_t)(b0 + rbase + r) * (Vn * Tn) + (size_t)v * Tn + t] =
            ((r == 0) ? a0 : (r == 1) ? a1 : (r == 2) ? a2 : a3) + pb;
}

// ---------------- launch ----------------
extern "C" void kernel_launch(void* const* d_in, const int* in_sizes, int n_in,
                              void* d_out, int out_size) {
    const float* fm     = (const float*)d_in[0];
    const float* pooled = (const float*)d_in[1];
    const float* gamma  = (const float*)d_in[2];
    const float* beta   = (const float*)d_in[3];
    const float* Wih    = (const float*)d_in[4];
    const float* Whh    = (const float*)d_in[5];
    const float* bih    = (const float*)d_in[6];
    const float* bhh    = (const float*)d_in[7];
    const float* emb    = (const float*)d_in[8];
    const float* attnw  = (const float*)d_in[9];
    // d_in[10] = attn_b: cancels in softmax (constant over the axis)
    const float* projw  = (const float*)d_in[11];
    const float* projb  = (const float*)d_in[12];
    const int*   sos    = (const int*)d_in[13];
    float* out = (float*)d_out;

    const int dynBytes = (25088 + 512) * 4;
    cudaFuncSetAttribute(k_init, cudaFuncAttributeMaxDynamicSharedMemorySize, dynBytes);
    cudaFuncSetAttribute(k_step, cudaFuncAttributeMaxDynamicSharedMemorySize, SMEM_STEP);

    k_init<<<Bn, 256, dynBytes>>>(fm, pooled, gamma, beta, attnw, sos);
    k_splitW<<<4096, 256>>>(Whh);
    k_e2<<<dim3(32, 2), 256>>>(emb, Wih, bih, bhh);
    k_tw<<<256, 256>>>(projw);

    for (int t = 0; t < Tn; t++) {
        k_step<<<256, 256, SMEM_STEP>>>(t, projb, out);
    }
    k_logits<<<128, 256>>>(Tn - 1, projb, out);
}